// round 9
// baseline (speedup 1.0000x reference)
#include <cuda_runtime.h>
#include <math.h>
#include <stdint.h>

#define NTOK   8192
#define DM     1024
#define NH     4
#define DQ     256
#define NSUB   128
#define TK     8
#define DL     256
#define DH     512
#define NEXP   16384
#define BN_EPS 1e-5f

// ---------------- scratch (static __device__: allocation-free) ----------------
__device__ float g_q[NTOK * 1024];          // 32 MB
__device__ float g_sum[1024];
__device__ float g_sqs[1024];
__device__ float g_a[1024];
__device__ float g_b[1024];
__device__ float g_sk1a[NH * 128 * 128];
__device__ float g_sk2a[NH * 128 * 128];
__device__ float g_bs1[NH * 128];
__device__ float g_bs2[NH * 128];
__device__ float g_s1[NTOK * NH * 128];     // 16 MB
__device__ float g_s2[NTOK * NH * 128];     // 16 MB
__device__ float g_probs[NTOK * NH * TK];
__device__ int   g_eidx[NTOK * NH * TK];
__device__ float g_H[NEXP * DH];            // 32 MB
__device__ float g_xp[NTOK * DH];           // 16 MB
__device__ float g_acc[NTOK * DH];          // 16 MB

__device__ __forceinline__ float gelu_exact(float x) {
    return 0.5f * x * (1.0f + erff(x * 0.70710678118654752440f));
}

// ---------------- tf32 helpers ----------------
__device__ __forceinline__ void split_tf32(float x, uint32_t& h, uint32_t& l) {
    uint32_t hb;
    asm("cvt.rna.tf32.f32 %0, %1;" : "=r"(hb) : "f"(x));
    h = hb;
    float lo = x - __uint_as_float(hb);
    l = __float_as_uint(lo);
}

__device__ __forceinline__ void mma8(float* d, const uint32_t* a, const uint32_t* b) {
    asm volatile(
        "mma.sync.aligned.m16n8k8.row.col.f32.tf32.tf32.f32 "
        "{%0,%1,%2,%3},{%4,%5,%6,%7},{%8,%9},{%0,%1,%2,%3};"
        : "+f"(d[0]), "+f"(d[1]), "+f"(d[2]), "+f"(d[3])
        : "r"(a[0]), "r"(a[1]), "r"(a[2]), "r"(a[3]), "r"(b[0]), "r"(b[1]));
}

// ---------------- tiny utility kernels ----------------
__global__ void zero_stats_kernel() {
    int i = threadIdx.x;
    g_sum[i] = 0.0f;
    g_sqs[i] = 0.0f;
}

// BatchNorm statistics over rows of g_q (8192 x 1024)
__global__ void bn_reduce_kernel() {
    int tid = threadIdx.x;             // 256
    int r0 = blockIdx.x * 64;          // 128 blocks
    float s0 = 0.f, s1 = 0.f, s2 = 0.f, s3 = 0.f;
    float q0 = 0.f, q1 = 0.f, q2 = 0.f, q3 = 0.f;
    for (int r = 0; r < 64; r++) {
        const float* row = g_q + (size_t)(r0 + r) * 1024;
        float v0 = row[tid];
        float v1 = row[tid + 256];
        float v2 = row[tid + 512];
        float v3 = row[tid + 768];
        s0 += v0; q0 += v0 * v0;
        s1 += v1; q1 += v1 * v1;
        s2 += v2; q2 += v2 * v2;
        s3 += v3; q3 += v3 * v3;
    }
    atomicAdd(&g_sum[tid],       s0);
    atomicAdd(&g_sum[tid + 256], s1);
    atomicAdd(&g_sum[tid + 512], s2);
    atomicAdd(&g_sum[tid + 768], s3);
    atomicAdd(&g_sqs[tid],       q0);
    atomicAdd(&g_sqs[tid + 256], q1);
    atomicAdd(&g_sqs[tid + 512], q2);
    atomicAdd(&g_sqs[tid + 768], q3);
}

__global__ void bn_finalize_kernel(const float* __restrict__ gamma,
                                   const float* __restrict__ beta) {
    int c = threadIdx.x;  // 1024
    float mean = g_sum[c] * (1.0f / NTOK);
    float var  = g_sqs[c] * (1.0f / NTOK) - mean * mean;
    float rstd = rsqrtf(var + BN_EPS);
    float a = gamma[c] * rstd;
    g_a[c] = a;
    g_b[c] = beta[c] - mean * a;
}

// Fold the BN affine into the score projection weights
__global__ void fold_sk_kernel(const float* __restrict__ sk1,
                               const float* __restrict__ sk2) {
    int h = blockIdx.x >> 7;      // 512 blocks
    int k = blockIdx.x & 127;
    int j = threadIdx.x;          // 128
    float w1 = sk1[k * 128 + j];
    float w2 = sk2[k * 128 + j];
    float a1 = g_a[h * 256 + j],       b1 = g_b[h * 256 + j];
    float a2 = g_a[h * 256 + 128 + j], b2 = g_b[h * 256 + 128 + j];
    g_sk1a[(h * 128 + k) * 128 + j] = w1 * a1;
    g_sk2a[(h * 128 + k) * 128 + j] = w2 * a2;
    float p1 = w1 * b1, p2 = w2 * b2;
    const unsigned FULL = 0xffffffffu;
    #pragma unroll
    for (int off = 16; off > 0; off >>= 1) {
        p1 += __shfl_down_sync(FULL, p1, off);
        p2 += __shfl_down_sync(FULL, p2, off);
    }
    __shared__ float sh[8];
    int w = j >> 5, l = j & 31;
    if (l == 0) { sh[w] = p1; sh[4 + w] = p2; }
    __syncthreads();
    if (j == 0) {
        g_bs1[h * 128 + k] = sh[0] + sh[1] + sh[2] + sh[3];
        g_bs2[h * 128 + k] = sh[4] + sh[5] + sh[6] + sh[7];
    }
}

// ---------------- 3xTF32 tensor-core GEMM ----------------
// 128x128 block tile, 8 warps (2x4), warp tile 64x32, K-tile 16, double-buffered.
// C[M,N] = A[M,K] * op(B) (+bias | gelu) * scale ; error-compensated tf32
// (hi*hi + lo*hi + hi*lo) -> ~1e-7 element error vs fp32.
// TRANSB=1: B is [N,K] row-major; TRANSB=0: B is [K,N] row-major.
// Requires M%128==0, N%128==0, K%16==0.
#define GSTR 20   // padded smem row stride (floats): conflict-free fragment loads

template <int TRANSB>
__global__ void __launch_bounds__(256)
gemm_tf32(const float* __restrict__ A, const float* __restrict__ B,
          float* __restrict__ C, const float* __restrict__ bias,
          int K, int lda, int ldb, int ldc, int epi, float scale) {
    __shared__ __align__(16) float As[2][128][GSTR];
    __shared__ __align__(16) float Bs[2][128][GSTR];

    int tid = threadIdx.x;
    int lane = tid & 31;
    int wid = tid >> 5;
    int wm = (wid >> 2) * 64;     // 0 or 64
    int wn = (wid & 3) * 32;      // 0,32,64,96
    int lq = lane >> 2, lr = lane & 3;

    int m0 = blockIdx.y * 128, n0 = blockIdx.x * 128;

    // global-load mapping
    int ar = tid >> 1;            // 0..127
    int ak = (tid & 1) * 8;       // 0 or 8
    const float* Aptr = A + (size_t)(m0 + ar) * lda + ak;

    const float* Bptr;
    int bn_r = 0, bk_c = 0;
    if (TRANSB) {
        Bptr = B + (size_t)(n0 + ar) * ldb + ak;
    } else {
        bk_c = tid & 15;          // 0..15
        bn_r = (tid >> 4) * 8;    // 0..120
        Bptr = B + (size_t)bk_c * ldb + n0 + bn_r;
    }

    float acc[4][4][4];
    #pragma unroll
    for (int mi = 0; mi < 4; mi++)
        #pragma unroll
        for (int ni = 0; ni < 4; ni++)
            #pragma unroll
            for (int t = 0; t < 4; t++) acc[mi][ni][t] = 0.0f;

    // ---- prefetch stage 0 ----
    float4 ra0 = *(const float4*)(Aptr);
    float4 ra1 = *(const float4*)(Aptr + 4);
    float4 rb0, rb1;
    if (TRANSB) {
        rb0 = *(const float4*)(Bptr);
        rb1 = *(const float4*)(Bptr + 4);
    } else {
        rb0 = *(const float4*)(Bptr);
        rb1 = *(const float4*)(Bptr + 4);
    }
    *(float4*)&As[0][ar][ak]     = ra0;
    *(float4*)&As[0][ar][ak + 4] = ra1;
    if (TRANSB) {
        *(float4*)&Bs[0][ar][ak]     = rb0;
        *(float4*)&Bs[0][ar][ak + 4] = rb1;
    } else {
        Bs[0][bn_r + 0][bk_c] = rb0.x;
        Bs[0][bn_r + 1][bk_c] = rb0.y;
        Bs[0][bn_r + 2][bk_c] = rb0.z;
        Bs[0][bn_r + 3][bk_c] = rb0.w;
        Bs[0][bn_r + 4][bk_c] = rb1.x;
        Bs[0][bn_r + 5][bk_c] = rb1.y;
        Bs[0][bn_r + 6][bk_c] = rb1.z;
        Bs[0][bn_r + 7][bk_c] = rb1.w;
    }
    __syncthreads();

    int nk = K >> 4;
    for (int kt = 0; kt < nk; kt++) {
        int cur = kt & 1;
        bool more = (kt + 1) < nk;
        if (more) {
            int koff = (kt + 1) * 16;
            ra0 = *(const float4*)(Aptr + koff);
            ra1 = *(const float4*)(Aptr + koff + 4);
            if (TRANSB) {
                rb0 = *(const float4*)(Bptr + koff);
                rb1 = *(const float4*)(Bptr + koff + 4);
            } else {
                rb0 = *(const float4*)(Bptr + (size_t)koff * ldb);
                rb1 = *(const float4*)(Bptr + (size_t)koff * ldb + 4);
            }
        }

        #pragma unroll
        for (int ks = 0; ks < 16; ks += 8) {
            uint32_t ah[4][4], al[4][4], bh[4][2], bl[4][2];
            #pragma unroll
            for (int mi = 0; mi < 4; mi++) {
                int r = wm + mi * 16 + lq;
                split_tf32(As[cur][r][ks + lr],         ah[mi][0], al[mi][0]);
                split_tf32(As[cur][r + 8][ks + lr],     ah[mi][1], al[mi][1]);
                split_tf32(As[cur][r][ks + lr + 4],     ah[mi][2], al[mi][2]);
                split_tf32(As[cur][r + 8][ks + lr + 4], ah[mi][3], al[mi][3]);
            }
            #pragma unroll
            for (int ni = 0; ni < 4; ni++) {
                int rn = wn + ni * 8 + lq;
                split_tf32(Bs[cur][rn][ks + lr],     bh[ni][0], bl[ni][0]);
                split_tf32(Bs[cur][rn][ks + lr + 4], bh[ni][1], bl[ni][1]);
            }
            #pragma unroll
            for (int mi = 0; mi < 4; mi++)
                #pragma unroll
                for (int ni = 0; ni < 4; ni++) {
                    mma8(acc[mi][ni], ah[mi], bh[ni]);
                    mma8(acc[mi][ni], al[mi], bh[ni]);
                    mma8(acc[mi][ni], ah[mi], bl[ni]);
                }
        }

        if (more) {
            int nxt = cur ^ 1;
            *(float4*)&As[nxt][ar][ak]     = ra0;
            *(float4*)&As[nxt][ar][ak + 4] = ra1;
            if (TRANSB) {
                *(float4*)&Bs[nxt][ar][ak]     = rb0;
                *(float4*)&Bs[nxt][ar][ak + 4] = rb1;
            } else {
                Bs[nxt][bn_r + 0][bk_c] = rb0.x;
                Bs[nxt][bn_r + 1][bk_c] = rb0.y;
                Bs[nxt][bn_r + 2][bk_c] = rb0.z;
                Bs[nxt][bn_r + 3][bk_c] = rb0.w;
                Bs[nxt][bn_r + 4][bk_c] = rb1.x;
                Bs[nxt][bn_r + 5][bk_c] = rb1.y;
                Bs[nxt][bn_r + 6][bk_c] = rb1.z;
                Bs[nxt][bn_r + 7][bk_c] = rb1.w;
            }
            __syncthreads();
        }
    }

    // ---- epilogue ----
    #pragma unroll
    for (int mi = 0; mi < 4; mi++) {
        #pragma unroll
        for (int h2 = 0; h2 < 2; h2++) {
            size_t row = (size_t)(m0 + wm + mi * 16 + lq + h2 * 8);
            #pragma unroll
            for (int ni = 0; ni < 4; ni++) {
                int c = n0 + wn + ni * 8 + 2 * lr;
                float v0 = acc[mi][ni][2 * h2];
                float v1 = acc[mi][ni][2 * h2 + 1];
                if (epi == 1) { v0 += bias[c]; v1 += bias[c + 1]; }
                else if (epi == 2) { v0 = gelu_exact(v0); v1 = gelu_exact(v1); }
                v0 *= scale; v1 *= scale;
                *(float2*)(C + row * ldc + c) = make_float2(v0, v1);
            }
        }
    }
}

// ---------------- FFMA SGEMM (kept for the small s1/s2 GEMMs) ----------------
__global__ void __launch_bounds__(256)
sgemm128(const float* __restrict__ A, const float* __restrict__ B,
         float* __restrict__ C, const float* __restrict__ bias,
         int K, int lda, int ldb, int ldc,
         long long aS, long long bS, long long cS, long long biasS,
         int transB, int epi, float scale) {
    A += (long long)blockIdx.z * aS;
    B += (long long)blockIdx.z * bS;
    C += (long long)blockIdx.z * cS;
    const float* biasz = bias ? (bias + (long long)blockIdx.z * biasS) : nullptr;

    __shared__ __align__(16) float As[2][8][128];
    __shared__ __align__(16) float Bs[2][8][128];

    int tid = threadIdx.x;
    int m0 = blockIdx.y * 128, n0 = blockIdx.x * 128;
    int tx = tid & 15, ty = tid >> 4;

    float acc[8][8];
    #pragma unroll
    for (int i = 0; i < 8; i++)
        #pragma unroll
        for (int j = 0; j < 8; j++) acc[i][j] = 0.0f;

    int hr = tid >> 1, hk = (tid & 1) * 4;
    int br = tid >> 5, bc = (tid & 31) * 4;

    const float* Aptr = A + (long long)(m0 + hr) * lda + hk;
    const float* Bptr;
    long long bstep;
    if (transB) { Bptr = B + (long long)(n0 + hr) * ldb + hk; bstep = 8; }
    else        { Bptr = B + (long long)br * ldb + n0 + bc;   bstep = 8LL * ldb; }

    float4 av = *(const float4*)Aptr;
    float4 bv = *(const float4*)Bptr;
    As[0][hk + 0][hr] = av.x; As[0][hk + 1][hr] = av.y;
    As[0][hk + 2][hr] = av.z; As[0][hk + 3][hr] = av.w;
    if (transB) {
        Bs[0][hk + 0][hr] = bv.x; Bs[0][hk + 1][hr] = bv.y;
        Bs[0][hk + 2][hr] = bv.z; Bs[0][hk + 3][hr] = bv.w;
    } else {
        *(float4*)&Bs[0][br][bc] = bv;
    }
    __syncthreads();

    int nk = K >> 3;
    for (int kt = 0; kt < nk; kt++) {
        int cur = kt & 1;
        bool more = (kt + 1 < nk);
        if (more) {
            av = *(const float4*)(Aptr + (long long)(kt + 1) * 8);
            bv = *(const float4*)(Bptr + (long long)(kt + 1) * bstep);
        }
        #pragma unroll
        for (int kk = 0; kk < 8; kk++) {
            float4 a0 = *(const float4*)&As[cur][kk][ty * 4];
            float4 a1 = *(const float4*)&As[cur][kk][ty * 4 + 64];
            float4 b0 = *(const float4*)&Bs[cur][kk][tx * 4];
            float4 b1 = *(const float4*)&Bs[cur][kk][tx * 4 + 64];
            float a[8] = {a0.x, a0.y, a0.z, a0.w, a1.x, a1.y, a1.z, a1.w};
            float b[8] = {b0.x, b0.y, b0.z, b0.w, b1.x, b1.y, b1.z, b1.w};
            #pragma unroll
            for (int i = 0; i < 8; i++)
                #pragma unroll
                for (int j = 0; j < 8; j++)
                    acc[i][j] = fmaf(a[i], b[j], acc[i][j]);
        }
        if (more) {
            int nxt = cur ^ 1;
            As[nxt][hk + 0][hr] = av.x; As[nxt][hk + 1][hr] = av.y;
            As[nxt][hk + 2][hr] = av.z; As[nxt][hk + 3][hr] = av.w;
            if (transB) {
                Bs[nxt][hk + 0][hr] = bv.x; Bs[nxt][hk + 1][hr] = bv.y;
                Bs[nxt][hk + 2][hr] = bv.z; Bs[nxt][hk + 3][hr] = bv.w;
            } else {
                *(float4*)&Bs[nxt][br][bc] = bv;
            }
            __syncthreads();
        }
    }

    #pragma unroll
    for (int i = 0; i < 8; i++) {
        long long row = m0 + ty * 4 + (i & 3) + (i >> 2) * 64;
        #pragma unroll
        for (int jh = 0; jh < 2; jh++) {
            int col = n0 + tx * 4 + jh * 64;
            float4 v;
            float* vp = &v.x;
            #pragma unroll
            for (int j = 0; j < 4; j++) {
                float t = acc[i][jh * 4 + j];
                if (epi == 1) t += biasz[col + j];
                else if (epi == 2) t = gelu_exact(t);
                vp[j] = t * scale;
            }
            *(float4*)(C + row * ldc + col) = v;
        }
    }
}

// ---------------- top-k machinery: one warp per (n,h) ----------------
__global__ void __launch_bounds__(256) topk_kernel() {
    const unsigned FULL = 0xffffffffu;
    int gw = (blockIdx.x * 256 + threadIdx.x) >> 5;   // 0..32767
    int lane = threadIdx.x & 31;
    const float* p1 = g_s1 + (size_t)gw * 128;
    const float* p2 = g_s2 + (size_t)gw * 128;

    float v1[4], v2[4];
    #pragma unroll
    for (int i = 0; i < 4; i++) {
        v1[i] = p1[lane + 32 * i];
        v2[i] = p2[lane + 32 * i];
    }

    float slot_v1 = 0.f, slot_v2 = 0.f;
    int   slot_i1 = 0,   slot_i2 = 0;
    #pragma unroll
    for (int t = 0; t < 16; t++) {
        {
            float bv = v1[0]; int bi = lane;
            #pragma unroll
            for (int i = 1; i < 4; i++)
                if (v1[i] > bv) { bv = v1[i]; bi = lane + 32 * i; }
            #pragma unroll
            for (int off = 16; off > 0; off >>= 1) {
                float ov = __shfl_down_sync(FULL, bv, off);
                int   oi = __shfl_down_sync(FULL, bi, off);
                if (ov > bv || (ov == bv && oi < bi)) { bv = ov; bi = oi; }
            }
            bv = __shfl_sync(FULL, bv, 0);
            bi = __shfl_sync(FULL, bi, 0);
            if (lane == t) { slot_v1 = bv; slot_i1 = bi; }
            int sl = bi >> 5, ol = bi & 31;
            if (lane == ol) {
                if      (sl == 0) v1[0] = -3.4e38f;
                else if (sl == 1) v1[1] = -3.4e38f;
                else if (sl == 2) v1[2] = -3.4e38f;
                else              v1[3] = -3.4e38f;
            }
        }
        {
            float bv = v2[0]; int bi = lane;
            #pragma unroll
            for (int i = 1; i < 4; i++)
                if (v2[i] > bv) { bv = v2[i]; bi = lane + 32 * i; }
            #pragma unroll
            for (int off = 16; off > 0; off >>= 1) {
                float ov = __shfl_down_sync(FULL, bv, off);
                int   oi = __shfl_down_sync(FULL, bi, off);
                if (ov > bv || (ov == bv && oi < bi)) { bv = ov; bi = oi; }
            }
            bv = __shfl_sync(FULL, bv, 0);
            bi = __shfl_sync(FULL, bi, 0);
            if (lane == t) { slot_v2 = bv; slot_i2 = bi; }
            int sl = bi >> 5, ol = bi & 31;
            if (lane == ol) {
                if      (sl == 0) v2[0] = -3.4e38f;
                else if (sl == 1) v2[1] = -3.4e38f;
                else if (sl == 2) v2[2] = -3.4e38f;
                else              v2[3] = -3.4e38f;
            }
        }
    }

    float cv[8];
    #pragma unroll
    for (int j = 0; j < 8; j++) {
        int c = lane + 32 * j;
        float a = __shfl_sync(FULL, slot_v1, c >> 4);
        float b = __shfl_sync(FULL, slot_v2, c & 15);
        cv[j] = a + b;
    }

    float sel_v = -3.4e38f; int sel_c = 0;
    #pragma unroll
    for (int t = 0; t < 8; t++) {
        float bv = cv[0]; int bc = lane;
        #pragma unroll
        for (int j = 1; j < 8; j++)
            if (cv[j] > bv) { bv = cv[j]; bc = lane + 32 * j; }
        #pragma unroll
        for (int off = 16; off > 0; off >>= 1) {
            float ov = __shfl_down_sync(FULL, bv, off);
            int   oc = __shfl_down_sync(FULL, bc, off);
            if (ov > bv || (ov == bv && oc < bc)) { bv = ov; bc = oc; }
        }
        bv = __shfl_sync(FULL, bv, 0);
        bc = __shfl_sync(FULL, bc, 0);
        if (lane == t) { sel_v = bv; sel_c = bc; }
        int sl = bc >> 5, ol = bc & 31;
        if (lane == ol) {
            switch (sl) {
                case 0: cv[0] = -3.4e38f; break;
                case 1: cv[1] = -3.4e38f; break;
                case 2: cv[2] = -3.4e38f; break;
                case 3: cv[3] = -3.4e38f; break;
                case 4: cv[4] = -3.4e38f; break;
                case 5: cv[5] = -3.4e38f; break;
                case 6: cv[6] = -3.4e38f; break;
                default: cv[7] = -3.4e38f; break;
            }
        }
    }

    float mv = (lane < 8) ? sel_v : -3.4e38f;
    #pragma unroll
    for (int off = 4; off > 0; off >>= 1)
        mv = fmaxf(mv, __shfl_xor_sync(FULL, mv, off));
    float ev = (lane < 8) ? expf(sel_v - mv) : 0.0f;
    float sum = ev;
    #pragma unroll
    for (int off = 4; off > 0; off >>= 1)
        sum += __shfl_xor_sync(FULL, sum, off);
    float p = ev / sum;

    int i1 = __shfl_sync(FULL, slot_i1, sel_c >> 4);
    int i2 = __shfl_sync(FULL, slot_i2, sel_c & 15);
    if (lane < 8) {
        g_probs[(size_t)gw * 8 + lane] = p;
        g_eidx [(size_t)gw * 8 + lane] = i1 * NSUB + i2;
    }
}

// ---------------- expert gather + dot + gelu + weighted accumulate ----------------
__global__ void __launch_bounds__(256) gather_kernel() {
    const unsigned FULL = 0xffffffffu;
    __shared__ float sx[DH];
    __shared__ float sacc[8][DH];
    int n = blockIdx.x;
    int tid = threadIdx.x;
    int w = tid >> 5, lane = tid & 31;

    sx[tid]       = g_xp[(size_t)n * DH + tid];
    sx[tid + 256] = g_xp[(size_t)n * DH + tid + 256];
    #pragma unroll
    for (int i = 0; i < 16; i++) sacc[w][lane + 32 * i] = 0.0f;
    __syncthreads();

    #pragma unroll
    for (int p = 0; p < 4; p++) {
        int idx = w * 4 + p;
        int e = g_eidx[(size_t)n * 32 + idx];
        float prob = g_probs[(size_t)n * 32 + idx];
        const float* hrow = g_H + (size_t)e * DH;
        float hv[16];
        float dot = 0.0f;
        #pragma unroll
        for (int i = 0; i < 16; i++) {
            hv[i] = hrow[lane + 32 * i];
            dot = fmaf(hv[i], sx[lane + 32 * i], dot);
        }
        #pragma unroll
        for (int off = 16; off > 0; off >>= 1)
            dot += __shfl_down_sync(FULL, dot, off);
        dot = __shfl_sync(FULL, dot, 0);
        float act = gelu_exact(dot) * prob;
        #pragma unroll
        for (int i = 0; i < 16; i++)
            sacc[w][lane + 32 * i] = fmaf(act, hv[i], sacc[w][lane + 32 * i]);
    }
    __syncthreads();

    for (int c = tid; c < DH; c += 256) {
        float s = 0.0f;
        #pragma unroll
        for (int ww = 0; ww < 8; ww++) s += sacc[ww][c];
        g_acc[(size_t)n * DH + c] = s;
    }
}

// ---------------- host launcher ----------------
extern "C" void kernel_launch(void* const* d_in, const int* in_sizes, int n_in,
                              void* d_out, int out_size) {
    (void)in_sizes; (void)n_in; (void)out_size;
    const float* x    = (const float*)d_in[0];
    const float* Wq   = (const float*)d_in[1];
    const float* bq   = (const float*)d_in[2];
    const float* gam  = (const float*)d_in[3];
    const float* bet  = (const float*)d_in[4];
    const float* sk1  = (const float*)d_in[5];
    const float* sk2  = (const float*)d_in[6];
    const float* lat  = (const float*)d_in[7];
    const float* W1   = (const float*)d_in[8];
    const float* W2   = (const float*)d_in[9];
    float* out = (float*)d_out;

    float *q, *bs1, *bs2, *s1, *s2, *sk1a, *sk2a, *H, *xp, *acc;
    cudaGetSymbolAddress((void**)&q,    g_q);
    cudaGetSymbolAddress((void**)&sk1a, g_sk1a);
    cudaGetSymbolAddress((void**)&sk2a, g_sk2a);
    cudaGetSymbolAddress((void**)&bs1,  g_bs1);
    cudaGetSymbolAddress((void**)&bs2,  g_bs2);
    cudaGetSymbolAddress((void**)&s1,   g_s1);
    cudaGetSymbolAddress((void**)&s2,   g_s2);
    cudaGetSymbolAddress((void**)&H,    g_H);
    cudaGetSymbolAddress((void**)&xp,   g_xp);
    cudaGetSymbolAddress((void**)&acc,  g_acc);

    // 1. zero BN accumulators
    zero_stats_kernel<<<1, 1024>>>();

    // 2. q = x @ Wq^T + bq   [8192,1024] x [1024,1024]^T   (3xTF32 tensor)
    gemm_tf32<1><<<dim3(8, 64), 256>>>(x, Wq, q, bq,
                                       1024, 1024, 1024, 1024, 1, 1.0f);

    // 3-5. BN stats, fold into affine, fold affine into score weights
    bn_reduce_kernel<<<128, 256>>>();
    bn_finalize_kernel<<<1, 1024>>>(gam, bet);
    fold_sk_kernel<<<512, 128>>>(sk1, sk2);

    // 6-7. s1, s2 = q_half @ (sk*a)^T + bias  (small K: FFMA path)
    sgemm128<<<dim3(1, 64, 4), 256>>>(q, sk1a, s1, bs1,
                                      128, 1024, 128, 512,
                                      256, 128 * 128, 128, 128, 1, 1, 1.0f);
    sgemm128<<<dim3(1, 64, 4), 256>>>(q + 128, sk2a, s2, bs2,
                                      128, 1024, 128, 512,
                                      256, 128 * 128, 128, 128, 1, 1, 1.0f);

    // 8. top-16 x top-16 -> top-8, softmax, expert indices
    topk_kernel<<<4096, 256>>>();

    // 9. H = gelu(latents @ W1)   [16384,256] x [256,512]   (3xTF32 tensor)
    gemm_tf32<0><<<dim3(4, 128), 256>>>(lat, W1, H, nullptr,
                                        256, 256, 512, 512, 2, 1.0f);

    // 10. x_proj = x @ W2[:, :1024]^T                        (3xTF32 tensor)
    gemm_tf32<1><<<dim3(4, 64), 256>>>(x, W2, xp, nullptr,
                                       1024, 1024, 2048, 512, 0, 1.0f);

    // 11. gather experts, act = gelu(<hg, x_proj>)*prob, acc = sum act*hg
    gather_kernel<<<NTOK, 256>>>();

    // 12. out = acc @ Wv / NUM_HEADS                         (3xTF32 tensor)
    gemm_tf32<0><<<dim3(8, 64), 256>>>(acc, W2 + 1024, out, nullptr,
                                       512, 512, 2048, 1024, 0, 0.25f);
}

// round 11
// speedup vs baseline: 1.5777x; 1.5777x over previous
#include <cuda_runtime.h>
#include <cuda_fp16.h>
#include <math.h>
#include <stdint.h>

#define NTOK   8192
#define DM     1024
#define NH     4
#define DQ     256
#define NSUB   128
#define TK     8
#define DL     256
#define DH     512
#define NEXP   16384
#define BN_EPS 1e-5f

// ---------------- scratch (static __device__: allocation-free) ----------------
__device__ float g_q[NTOK * 1024];          // 32 MB
__device__ float g_sum[1024];
__device__ float g_sqs[1024];
__device__ float g_a[1024];
__device__ float g_b[1024];
__device__ float g_sk1a[NH * 128 * 128];
__device__ float g_sk2a[NH * 128 * 128];
__device__ float g_bs1[NH * 128];
__device__ float g_bs2[NH * 128];
__device__ float g_s1[NTOK * NH * 128];     // 16 MB
__device__ float g_s2[NTOK * NH * 128];     // 16 MB
__device__ float g_probs[NTOK * NH * TK];
__device__ int   g_eidx[NTOK * NH * TK];
__device__ float g_H[NEXP * DH];            // 32 MB
__device__ float g_xp[NTOK * DH];           // 16 MB
__device__ float g_acc[NTOK * DH];          // 16 MB
__device__ float g_W1T[DH * DL];            // 512x256  (W1^T, K-major)
__device__ float g_WvT[1024 * DH];          // 1024x512 (Wv^T, K-major)

__device__ __forceinline__ float gelu_exact(float x) {
    return 0.5f * x * (1.0f + erff(x * 0.70710678118654752440f));
}

// ---------------- fp16x3 helpers ----------------
// Split two fp32 values into packed-half hi word and lo (residual) word.
__device__ __forceinline__ void split2(float x, float y, uint32_t& hi, uint32_t& lo) {
    __half hx = __float2half_rn(x);
    __half hy = __float2half_rn(y);
    float lx = x - __half2float(hx);
    float ly = y - __half2float(hy);
    __half lxh = __float2half_rn(lx);
    __half lyh = __float2half_rn(ly);
    hi = (uint32_t)__half_as_ushort(hx) | ((uint32_t)__half_as_ushort(hy) << 16);
    lo = (uint32_t)__half_as_ushort(lxh) | ((uint32_t)__half_as_ushort(lyh) << 16);
}

__device__ __forceinline__ void hmma(float* d, const uint32_t* a, const uint32_t* b) {
    asm volatile(
        "mma.sync.aligned.m16n8k16.row.col.f32.f16.f16.f32 "
        "{%0,%1,%2,%3},{%4,%5,%6,%7},{%8,%9},{%0,%1,%2,%3};"
        : "+f"(d[0]), "+f"(d[1]), "+f"(d[2]), "+f"(d[3])
        : "r"(a[0]), "r"(a[1]), "r"(a[2]), "r"(a[3]), "r"(b[0]), "r"(b[1]));
}

// ---------------- fp16x3 HMMA GEMM ----------------
// C[M,N] = A[M,K] * B^T (+bias | gelu) * scale ; B is [N,K] row-major (K-major).
// Block tile 128x128, 8 warps (2x4), warp tile 64x32, K-chunk 32, double buffered.
// SMEM per stage: Ah, Al, Bh, Bl each [128 rows][20 u32] (16 used = 32 halves + pad).
// Fragment loads are conflict-free under stride 20 (verified bank mapping).
// Error: missing Al*Bl term ~2^-22 relative -> fp32-class accuracy.
#define HSTR 20
#define MAT_U32 (128 * HSTR)
#define STAGE_U32 (4 * MAT_U32)

__global__ void __launch_bounds__(256)
gemm_h3(const float* __restrict__ A, const float* __restrict__ B,
        float* __restrict__ C, const float* __restrict__ bias,
        int K, int lda, int ldb, int ldc, int epi, float scale) {
    extern __shared__ uint32_t smu[];

    int tid = threadIdx.x;
    int lane = tid & 31;
    int wid = tid >> 5;
    int wm = (wid >> 2) * 64;     // 0 or 64
    int wn = (wid & 3) * 32;      // 0,32,64,96
    int g = lane >> 2, tg = lane & 3;

    int m0 = blockIdx.y * 128, n0 = blockIdx.x * 128;

    int r_ld = tid >> 1;                 // 0..127 (A/B row for this thread)
    int c4 = (tid & 1) * 4;              // unused slot marker (2 float4 per row-half)

    float acc[4][4][4];
    #pragma unroll
    for (int mi = 0; mi < 4; mi++)
        #pragma unroll
        for (int ni = 0; ni < 4; ni++)
            #pragma unroll
            for (int t = 0; t < 4; t++) acc[mi][ni][t] = 0.0f;

    // Each thread loads: A row r_ld, k-quad (tid&1)*4 -> 2 float4 (8 floats? no:
    // 128 rows x 32 k = 4096 floats = 1024 float4; 256 threads -> 4 float4 each.
    // Mapping: f = tid + 256*i, row = f>>3, quad = f&7 (k = quad*4).
    auto gaddrA = [&](int i, int k0) {
        int f = tid + 256 * i;
        return A + (size_t)(m0 + (f >> 3)) * lda + k0 + (f & 7) * 4;
    };
    auto gaddrB = [&](int i, int k0) {
        int f = tid + 256 * i;
        return B + (size_t)(n0 + (f >> 3)) * ldb + k0 + (f & 7) * 4;
    };
    auto store_stage = [&](int s, const float4* va, const float4* vb) {
        uint32_t* st = smu + s * STAGE_U32;
        #pragma unroll
        for (int i = 0; i < 4; i++) {
            int f = tid + 256 * i;
            int r = f >> 3, q = f & 7;
            uint32_t h0, l0, h1, l1;
            split2(va[i].x, va[i].y, h0, l0);
            split2(va[i].z, va[i].w, h1, l1);
            st[r * HSTR + q * 2]               = h0;
            st[r * HSTR + q * 2 + 1]           = h1;
            st[MAT_U32 + r * HSTR + q * 2]     = l0;
            st[MAT_U32 + r * HSTR + q * 2 + 1] = l1;
            split2(vb[i].x, vb[i].y, h0, l0);
            split2(vb[i].z, vb[i].w, h1, l1);
            st[2 * MAT_U32 + r * HSTR + q * 2]     = h0;
            st[2 * MAT_U32 + r * HSTR + q * 2 + 1] = h1;
            st[3 * MAT_U32 + r * HSTR + q * 2]     = l0;
            st[3 * MAT_U32 + r * HSTR + q * 2 + 1] = l1;
        }
    };

    // prefetch + store stage 0
    float4 va[4], vb[4];
    #pragma unroll
    for (int i = 0; i < 4; i++) { va[i] = *(const float4*)gaddrA(i, 0); vb[i] = *(const float4*)gaddrB(i, 0); }
    store_stage(0, va, vb);
    __syncthreads();

    int nkt = K >> 5;
    for (int kt = 0; kt < nkt; kt++) {
        int cur = kt & 1;
        bool more = (kt + 1) < nkt;
        if (more) {
            int k0 = (kt + 1) * 32;
            #pragma unroll
            for (int i = 0; i < 4; i++) { va[i] = *(const float4*)gaddrA(i, k0); vb[i] = *(const float4*)gaddrB(i, k0); }
        }

        const uint32_t* st = smu + cur * STAGE_U32;
        #pragma unroll
        for (int ks = 0; ks < 2; ks++) {          // two K16 steps per chunk
            int kc = ks * 8;
            uint32_t ah[4][4], al[4][4], bh[4][2], bl[4][2];
            #pragma unroll
            for (int mi = 0; mi < 4; mi++) {
                int r = wm + mi * 16 + g;
                ah[mi][0] = st[r * HSTR + kc + tg];
                ah[mi][1] = st[(r + 8) * HSTR + kc + tg];
                ah[mi][2] = st[r * HSTR + kc + tg + 4];
                ah[mi][3] = st[(r + 8) * HSTR + kc + tg + 4];
                al[mi][0] = st[MAT_U32 + r * HSTR + kc + tg];
                al[mi][1] = st[MAT_U32 + (r + 8) * HSTR + kc + tg];
                al[mi][2] = st[MAT_U32 + r * HSTR + kc + tg + 4];
                al[mi][3] = st[MAT_U32 + (r + 8) * HSTR + kc + tg + 4];
            }
            #pragma unroll
            for (int ni = 0; ni < 4; ni++) {
                int rn = wn + ni * 8 + g;
                bh[ni][0] = st[2 * MAT_U32 + rn * HSTR + kc + tg];
                bh[ni][1] = st[2 * MAT_U32 + rn * HSTR + kc + tg + 4];
                bl[ni][0] = st[3 * MAT_U32 + rn * HSTR + kc + tg];
                bl[ni][1] = st[3 * MAT_U32 + rn * HSTR + kc + tg + 4];
            }
            #pragma unroll
            for (int mi = 0; mi < 4; mi++)
                #pragma unroll
                for (int ni = 0; ni < 4; ni++) {
                    hmma(acc[mi][ni], ah[mi], bh[ni]);
                    hmma(acc[mi][ni], al[mi], bh[ni]);
                    hmma(acc[mi][ni], ah[mi], bl[ni]);
                }
        }

        if (more) {
            __syncthreads();                      // all reads of nxt-stage smem done (prev iter)
            store_stage(cur ^ 1, va, vb);
            __syncthreads();
        }
    }

    // ---- epilogue ----
    #pragma unroll
    for (int mi = 0; mi < 4; mi++) {
        #pragma unroll
        for (int h2 = 0; h2 < 2; h2++) {
            size_t row = (size_t)(m0 + wm + mi * 16 + g + h2 * 8);
            #pragma unroll
            for (int ni = 0; ni < 4; ni++) {
                int c = n0 + wn + ni * 8 + 2 * tg;
                float v0 = acc[mi][ni][2 * h2];
                float v1 = acc[mi][ni][2 * h2 + 1];
                if (epi == 1) { v0 += bias[c]; v1 += bias[c + 1]; }
                else if (epi == 2) { v0 = gelu_exact(v0); v1 = gelu_exact(v1); }
                v0 *= scale; v1 *= scale;
                *(float2*)(C + row * ldc + c) = make_float2(v0, v1);
            }
        }
    }
    (void)c4; (void)r_ld;
}

// ---------------- tiled transpose: dst[c][r] = src[r][c] ----------------
__global__ void transpose_kernel(const float* __restrict__ src, float* __restrict__ dst,
                                 int R, int C, int lds) {
    __shared__ float t[32][33];
    int c0 = blockIdx.x * 32, r0 = blockIdx.y * 32;
    #pragma unroll
    for (int i = 0; i < 32; i += 8)
        t[threadIdx.y + i][threadIdx.x] =
            src[(size_t)(r0 + threadIdx.y + i) * lds + c0 + threadIdx.x];
    __syncthreads();
    #pragma unroll
    for (int i = 0; i < 32; i += 8)
        dst[(size_t)(c0 + threadIdx.y + i) * R + r0 + threadIdx.x] =
            t[threadIdx.x][threadIdx.y + i];
}

// ---------------- tiny utility kernels ----------------
__global__ void zero_stats_kernel() {
    int i = threadIdx.x;
    g_sum[i] = 0.0f;
    g_sqs[i] = 0.0f;
}

__global__ void bn_reduce_kernel() {
    int tid = threadIdx.x;             // 256
    int r0 = blockIdx.x * 64;          // 128 blocks
    float s0 = 0.f, s1 = 0.f, s2 = 0.f, s3 = 0.f;
    float q0 = 0.f, q1 = 0.f, q2 = 0.f, q3 = 0.f;
    for (int r = 0; r < 64; r++) {
        const float* row = g_q + (size_t)(r0 + r) * 1024;
        float v0 = row[tid];
        float v1 = row[tid + 256];
        float v2 = row[tid + 512];
        float v3 = row[tid + 768];
        s0 += v0; q0 += v0 * v0;
        s1 += v1; q1 += v1 * v1;
        s2 += v2; q2 += v2 * v2;
        s3 += v3; q3 += v3 * v3;
    }
    atomicAdd(&g_sum[tid],       s0);
    atomicAdd(&g_sum[tid + 256], s1);
    atomicAdd(&g_sum[tid + 512], s2);
    atomicAdd(&g_sum[tid + 768], s3);
    atomicAdd(&g_sqs[tid],       q0);
    atomicAdd(&g_sqs[tid + 256], q1);
    atomicAdd(&g_sqs[tid + 512], q2);
    atomicAdd(&g_sqs[tid + 768], q3);
}

__global__ void bn_finalize_kernel(const float* __restrict__ gamma,
                                   const float* __restrict__ beta) {
    int c = threadIdx.x;  // 1024
    float mean = g_sum[c] * (1.0f / NTOK);
    float var  = g_sqs[c] * (1.0f / NTOK) - mean * mean;
    float rstd = rsqrtf(var + BN_EPS);
    float a = gamma[c] * rstd;
    g_a[c] = a;
    g_b[c] = beta[c] - mean * a;
}

__global__ void fold_sk_kernel(const float* __restrict__ sk1,
                               const float* __restrict__ sk2) {
    int h = blockIdx.x >> 7;      // 512 blocks
    int k = blockIdx.x & 127;
    int j = threadIdx.x;          // 128
    float w1 = sk1[k * 128 + j];
    float w2 = sk2[k * 128 + j];
    float a1 = g_a[h * 256 + j],       b1 = g_b[h * 256 + j];
    float a2 = g_a[h * 256 + 128 + j], b2 = g_b[h * 256 + 128 + j];
    g_sk1a[(h * 128 + k) * 128 + j] = w1 * a1;
    g_sk2a[(h * 128 + k) * 128 + j] = w2 * a2;
    float p1 = w1 * b1, p2 = w2 * b2;
    const unsigned FULL = 0xffffffffu;
    #pragma unroll
    for (int off = 16; off > 0; off >>= 1) {
        p1 += __shfl_down_sync(FULL, p1, off);
        p2 += __shfl_down_sync(FULL, p2, off);
    }
    __shared__ float sh[8];
    int w = j >> 5, l = j & 31;
    if (l == 0) { sh[w] = p1; sh[4 + w] = p2; }
    __syncthreads();
    if (j == 0) {
        g_bs1[h * 128 + k] = sh[0] + sh[1] + sh[2] + sh[3];
        g_bs2[h * 128 + k] = sh[4] + sh[5] + sh[6] + sh[7];
    }
}

// ---------------- FFMA SGEMM (s1/s2 — numerics preserved) ----------------
__global__ void __launch_bounds__(256)
sgemm128(const float* __restrict__ A, const float* __restrict__ B,
         float* __restrict__ C, const float* __restrict__ bias,
         int K, int lda, int ldb, int ldc,
         long long aS, long long bS, long long cS, long long biasS,
         int transB, int epi, float scale) {
    A += (long long)blockIdx.z * aS;
    B += (long long)blockIdx.z * bS;
    C += (long long)blockIdx.z * cS;
    const float* biasz = bias ? (bias + (long long)blockIdx.z * biasS) : nullptr;

    __shared__ __align__(16) float As[2][8][128];
    __shared__ __align__(16) float Bs[2][8][128];

    int tid = threadIdx.x;
    int m0 = blockIdx.y * 128, n0 = blockIdx.x * 128;
    int tx = tid & 15, ty = tid >> 4;

    float acc[8][8];
    #pragma unroll
    for (int i = 0; i < 8; i++)
        #pragma unroll
        for (int j = 0; j < 8; j++) acc[i][j] = 0.0f;

    int hr = tid >> 1, hk = (tid & 1) * 4;
    int br = tid >> 5, bc = (tid & 31) * 4;

    const float* Aptr = A + (long long)(m0 + hr) * lda + hk;
    const float* Bptr;
    long long bstep;
    if (transB) { Bptr = B + (long long)(n0 + hr) * ldb + hk; bstep = 8; }
    else        { Bptr = B + (long long)br * ldb + n0 + bc;   bstep = 8LL * ldb; }

    float4 av = *(const float4*)Aptr;
    float4 bv = *(const float4*)Bptr;
    As[0][hk + 0][hr] = av.x; As[0][hk + 1][hr] = av.y;
    As[0][hk + 2][hr] = av.z; As[0][hk + 3][hr] = av.w;
    if (transB) {
        Bs[0][hk + 0][hr] = bv.x; Bs[0][hk + 1][hr] = bv.y;
        Bs[0][hk + 2][hr] = bv.z; Bs[0][hk + 3][hr] = bv.w;
    } else {
        *(float4*)&Bs[0][br][bc] = bv;
    }
    __syncthreads();

    int nk = K >> 3;
    for (int kt = 0; kt < nk; kt++) {
        int cur = kt & 1;
        bool more = (kt + 1 < nk);
        if (more) {
            av = *(const float4*)(Aptr + (long long)(kt + 1) * 8);
            bv = *(const float4*)(Bptr + (long long)(kt + 1) * bstep);
        }
        #pragma unroll
        for (int kk = 0; kk < 8; kk++) {
            float4 a0 = *(const float4*)&As[cur][kk][ty * 4];
            float4 a1 = *(const float4*)&As[cur][kk][ty * 4 + 64];
            float4 b0 = *(const float4*)&Bs[cur][kk][tx * 4];
            float4 b1 = *(const float4*)&Bs[cur][kk][tx * 4 + 64];
            float a[8] = {a0.x, a0.y, a0.z, a0.w, a1.x, a1.y, a1.z, a1.w};
            float b[8] = {b0.x, b0.y, b0.z, b0.w, b1.x, b1.y, b1.z, b1.w};
            #pragma unroll
            for (int i = 0; i < 8; i++)
                #pragma unroll
                for (int j = 0; j < 8; j++)
                    acc[i][j] = fmaf(a[i], b[j], acc[i][j]);
        }
        if (more) {
            int nxt = cur ^ 1;
            As[nxt][hk + 0][hr] = av.x; As[nxt][hk + 1][hr] = av.y;
            As[nxt][hk + 2][hr] = av.z; As[nxt][hk + 3][hr] = av.w;
            if (transB) {
                Bs[nxt][hk + 0][hr] = bv.x; Bs[nxt][hk + 1][hr] = bv.y;
                Bs[nxt][hk + 2][hr] = bv.z; Bs[nxt][hk + 3][hr] = bv.w;
            } else {
                *(float4*)&Bs[nxt][br][bc] = bv;
            }
            __syncthreads();
        }
    }

    #pragma unroll
    for (int i = 0; i < 8; i++) {
        long long row = m0 + ty * 4 + (i & 3) + (i >> 2) * 64;
        #pragma unroll
        for (int jh = 0; jh < 2; jh++) {
            int col = n0 + tx * 4 + jh * 64;
            float4 v;
            float* vp = &v.x;
            #pragma unroll
            for (int j = 0; j < 4; j++) {
                float t = acc[i][jh * 4 + j];
                if (epi == 1) t += biasz[col + j];
                else if (epi == 2) t = gelu_exact(t);
                vp[j] = t * scale;
            }
            *(float4*)(C + row * ldc + col) = v;
        }
    }
}

// ---------------- top-k machinery: one warp per (n,h) ----------------
__global__ void __launch_bounds__(256) topk_kernel() {
    const unsigned FULL = 0xffffffffu;
    int gw = (blockIdx.x * 256 + threadIdx.x) >> 5;   // 0..32767
    int lane = threadIdx.x & 31;
    const float* p1 = g_s1 + (size_t)gw * 128;
    const float* p2 = g_s2 + (size_t)gw * 128;

    float v1[4], v2[4];
    #pragma unroll
    for (int i = 0; i < 4; i++) {
        v1[i] = p1[lane + 32 * i];
        v2[i] = p2[lane + 32 * i];
    }

    float slot_v1 = 0.f, slot_v2 = 0.f;
    int   slot_i1 = 0,   slot_i2 = 0;
    #pragma unroll
    for (int t = 0; t < 16; t++) {
        {
            float bv = v1[0]; int bi = lane;
            #pragma unroll
            for (int i = 1; i < 4; i++)
                if (v1[i] > bv) { bv = v1[i]; bi = lane + 32 * i; }
            #pragma unroll
            for (int off = 16; off > 0; off >>= 1) {
                float ov = __shfl_down_sync(FULL, bv, off);
                int   oi = __shfl_down_sync(FULL, bi, off);
                if (ov > bv || (ov == bv && oi < bi)) { bv = ov; bi = oi; }
            }
            bv = __shfl_sync(FULL, bv, 0);
            bi = __shfl_sync(FULL, bi, 0);
            if (lane == t) { slot_v1 = bv; slot_i1 = bi; }
            int sl = bi >> 5, ol = bi & 31;
            if (lane == ol) {
                if      (sl == 0) v1[0] = -3.4e38f;
                else if (sl == 1) v1[1] = -3.4e38f;
                else if (sl == 2) v1[2] = -3.4e38f;
                else              v1[3] = -3.4e38f;
            }
        }
        {
            float bv = v2[0]; int bi = lane;
            #pragma unroll
            for (int i = 1; i < 4; i++)
                if (v2[i] > bv) { bv = v2[i]; bi = lane + 32 * i; }
            #pragma unroll
            for (int off = 16; off > 0; off >>= 1) {
                float ov = __shfl_down_sync(FULL, bv, off);
                int   oi = __shfl_down_sync(FULL, bi, off);
                if (ov > bv || (ov == bv && oi < bi)) { bv = ov; bi = oi; }
            }
            bv = __shfl_sync(FULL, bv, 0);
            bi = __shfl_sync(FULL, bi, 0);
            if (lane == t) { slot_v2 = bv; slot_i2 = bi; }
            int sl = bi >> 5, ol = bi & 31;
            if (lane == ol) {
                if      (sl == 0) v2[0] = -3.4e38f;
                else if (sl == 1) v2[1] = -3.4e38f;
                else if (sl == 2) v2[2] = -3.4e38f;
                else              v2[3] = -3.4e38f;
            }
        }
    }

    float cv[8];
    #pragma unroll
    for (int j = 0; j < 8; j++) {
        int c = lane + 32 * j;
        float a = __shfl_sync(FULL, slot_v1, c >> 4);
        float b = __shfl_sync(FULL, slot_v2, c & 15);
        cv[j] = a + b;
    }

    float sel_v = -3.4e38f; int sel_c = 0;
    #pragma unroll
    for (int t = 0; t < 8; t++) {
        float bv = cv[0]; int bc = lane;
        #pragma unroll
        for (int j = 1; j < 8; j++)
            if (cv[j] > bv) { bv = cv[j]; bc = lane + 32 * j; }
        #pragma unroll
        for (int off = 16; off > 0; off >>= 1) {
            float ov = __shfl_down_sync(FULL, bv, off);
            int   oc = __shfl_down_sync(FULL, bc, off);
            if (ov > bv || (ov == bv && oc < bc)) { bv = ov; bc = oc; }
        }
        bv = __shfl_sync(FULL, bv, 0);
        bc = __shfl_sync(FULL, bc, 0);
        if (lane == t) { sel_v = bv; sel_c = bc; }
        int sl = bc >> 5, ol = bc & 31;
        if (lane == ol) {
            switch (sl) {
                case 0: cv[0] = -3.4e38f; break;
                case 1: cv[1] = -3.4e38f; break;
                case 2: cv[2] = -3.4e38f; break;
                case 3: cv[3] = -3.4e38f; break;
                case 4: cv[4] = -3.4e38f; break;
                case 5: cv[5] = -3.4e38f; break;
                case 6: cv[6] = -3.4e38f; break;
                default: cv[7] = -3.4e38f; break;
            }
        }
    }

    float mv = (lane < 8) ? sel_v : -3.4e38f;
    #pragma unroll
    for (int off = 4; off > 0; off >>= 1)
        mv = fmaxf(mv, __shfl_xor_sync(FULL, mv, off));
    float ev = (lane < 8) ? expf(sel_v - mv) : 0.0f;
    float sum = ev;
    #pragma unroll
    for (int off = 4; off > 0; off >>= 1)
        sum += __shfl_xor_sync(FULL, sum, off);
    float p = ev / sum;

    int i1 = __shfl_sync(FULL, slot_i1, sel_c >> 4);
    int i2 = __shfl_sync(FULL, slot_i2, sel_c & 15);
    if (lane < 8) {
        g_probs[(size_t)gw * 8 + lane] = p;
        g_eidx [(size_t)gw * 8 + lane] = i1 * NSUB + i2;
    }
}

// ---------------- expert gather + dot + gelu + weighted accumulate ----------------
__global__ void __launch_bounds__(256) gather_kernel() {
    const unsigned FULL = 0xffffffffu;
    __shared__ float sx[DH];
    __shared__ float sacc[8][DH];
    int n = blockIdx.x;
    int tid = threadIdx.x;
    int w = tid >> 5, lane = tid & 31;

    sx[tid]       = g_xp[(size_t)n * DH + tid];
    sx[tid + 256] = g_xp[(size_t)n * DH + tid + 256];
    #pragma unroll
    for (int i = 0; i < 16; i++) sacc[w][lane + 32 * i] = 0.0f;
    __syncthreads();

    #pragma unroll
    for (int p = 0; p < 4; p++) {
        int idx = w * 4 + p;
        int e = g_eidx[(size_t)n * 32 + idx];
        float prob = g_probs[(size_t)n * 32 + idx];
        const float* hrow = g_H + (size_t)e * DH;
        float hv[16];
        float dot = 0.0f;
        #pragma unroll
        for (int i = 0; i < 16; i++) {
            hv[i] = hrow[lane + 32 * i];
            dot = fmaf(hv[i], sx[lane + 32 * i], dot);
        }
        #pragma unroll
        for (int off = 16; off > 0; off >>= 1)
            dot += __shfl_down_sync(FULL, dot, off);
        dot = __shfl_sync(FULL, dot, 0);
        float act = gelu_exact(dot) * prob;
        #pragma unroll
        for (int i = 0; i < 16; i++)
            sacc[w][lane + 32 * i] = fmaf(act, hv[i], sacc[w][lane + 32 * i]);
    }
    __syncthreads();

    for (int c = tid; c < DH; c += 256) {
        float s = 0.0f;
        #pragma unroll
        for (int ww = 0; ww < 8; ww++) s += sacc[ww][c];
        g_acc[(size_t)n * DH + c] = s;
    }
}

// ---------------- host launcher ----------------
extern "C" void kernel_launch(void* const* d_in, const int* in_sizes, int n_in,
                              void* d_out, int out_size) {
    (void)in_sizes; (void)n_in; (void)out_size;
    const float* x    = (const float*)d_in[0];
    const float* Wq   = (const float*)d_in[1];
    const float* bq   = (const float*)d_in[2];
    const float* gam  = (const float*)d_in[3];
    const float* bet  = (const float*)d_in[4];
    const float* sk1  = (const float*)d_in[5];
    const float* sk2  = (const float*)d_in[6];
    const float* lat  = (const float*)d_in[7];
    const float* W1   = (const float*)d_in[8];
    const float* W2   = (const float*)d_in[9];
    float* out = (float*)d_out;

    float *q, *bs1, *bs2, *s1, *s2, *sk1a, *sk2a, *H, *xp, *acc, *W1T, *WvT;
    cudaGetSymbolAddress((void**)&q,    g_q);
    cudaGetSymbolAddress((void**)&sk1a, g_sk1a);
    cudaGetSymbolAddress((void**)&sk2a, g_sk2a);
    cudaGetSymbolAddress((void**)&bs1,  g_bs1);
    cudaGetSymbolAddress((void**)&bs2,  g_bs2);
    cudaGetSymbolAddress((void**)&s1,   g_s1);
    cudaGetSymbolAddress((void**)&s2,   g_s2);
    cudaGetSymbolAddress((void**)&H,    g_H);
    cudaGetSymbolAddress((void**)&xp,   g_xp);
    cudaGetSymbolAddress((void**)&acc,  g_acc);
    cudaGetSymbolAddress((void**)&W1T,  g_W1T);
    cudaGetSymbolAddress((void**)&WvT,  g_WvT);

    const int h3_smem = 2 * STAGE_U32 * 4;   // 81920 bytes
    cudaFuncSetAttribute(gemm_h3, cudaFuncAttributeMaxDynamicSharedMemorySize, h3_smem);

    // 1. zero BN accumulators + pre-transpose W1 / Wv to K-major
    zero_stats_kernel<<<1, 1024>>>();
    transpose_kernel<<<dim3(16, 8),  dim3(32, 8)>>>(W1, W1T, 256, 512, 512);
    transpose_kernel<<<dim3(32, 16), dim3(32, 8)>>>(W2 + 1024, WvT, 512, 1024, 2048);

    // 2. q = x @ Wq^T + bq   [8192,1024]x[1024,1024]^T   (fp16x3 HMMA)
    gemm_h3<<<dim3(8, 64), 256, h3_smem>>>(x, Wq, q, bq,
                                           1024, 1024, 1024, 1024, 1, 1.0f);

    // 3-5. BN stats, fold into affine, fold affine into score weights
    bn_reduce_kernel<<<128, 256>>>();
    bn_finalize_kernel<<<1, 1024>>>(gam, bet);
    fold_sk_kernel<<<512, 128>>>(sk1, sk2);

    // 6-7. s1, s2 (FFMA — selection-path numerics preserved)
    sgemm128<<<dim3(1, 64, 4), 256>>>(q, sk1a, s1, bs1,
                                      128, 1024, 128, 512,
                                      256, 128 * 128, 128, 128, 1, 1, 1.0f);
    sgemm128<<<dim3(1, 64, 4), 256>>>(q + 128, sk2a, s2, bs2,
                                      128, 1024, 128, 512,
                                      256, 128 * 128, 128, 128, 1, 1, 1.0f);

    // 8. top-16 x top-16 -> top-8, softmax, expert indices
    topk_kernel<<<4096, 256>>>();

    // 9. H = gelu(latents @ W1)   [16384,256]x[512,256]^T   (fp16x3 HMMA)
    gemm_h3<<<dim3(4, 128), 256, h3_smem>>>(lat, W1T, H, nullptr,
                                            256, 256, 256, 512, 2, 1.0f);

    // 10. x_proj = x @ W2[:, :1024]^T   [8192,1024]x[512,1024]^T (fp16x3 HMMA)
    gemm_h3<<<dim3(4, 64), 256, h3_smem>>>(x, W2, xp, nullptr,
                                           1024, 1024, 2048, 512, 0, 1.0f);

    // 11. gather experts, act = gelu(<hg, x_proj>)*prob, acc = sum act*hg
    gather_kernel<<<NTOK, 256>>>();

    // 12. out = acc @ Wv / NUM_HEADS  [8192,512]x[1024,512]^T  (fp16x3 HMMA)
    gemm_h3<<<dim3(8, 64), 256, h3_smem>>>(acc, WvT, out, nullptr,
                                           512, 512, 512, 1024, 0, 0.25f);
}

// round 14
// speedup vs baseline: 1.8125x; 1.1489x over previous
#include <cuda_runtime.h>
#include <cuda_fp16.h>
#include <math.h>
#include <stdint.h>

#define NTOK   8192
#define DM     1024
#define NH     4
#define DQ     256
#define NSUB   128
#define TK     8
#define DL     256
#define DH     512
#define NEXP   16384
#define BN_EPS 1e-5f

// ---------------- scratch (static __device__: allocation-free) ----------------
__device__ float g_q[NTOK * 1024];          // 32 MB
__device__ float g_sum[1024];
__device__ float g_sqs[1024];
__device__ float g_a[1024];
__device__ float g_b[1024];
__device__ float g_sk1a[NH * 128 * 128];
__device__ float g_sk2a[NH * 128 * 128];
__device__ float g_bs1[NH * 128];
__device__ float g_bs2[NH * 128];
__device__ float g_s1[NTOK * NH * 128];     // 16 MB
__device__ float g_s2[NTOK * NH * 128];     // 16 MB
__device__ float g_probs[NTOK * NH * TK];
__device__ int   g_eidx[NTOK * NH * TK];
__device__ float g_H[NEXP * DH];            // 32 MB
__device__ float g_xp[NTOK * DH];           // 16 MB
__device__ float g_acc[NTOK * DH];          // 16 MB

// pre-split half hi/lo operand buffers
__device__ __half g_xh[NTOK * DM],  g_xl[NTOK * DM];      // 16 MB each
__device__ __half g_Wqh[1024 * 1024], g_Wql[1024 * 1024];
__device__ __half g_lath[NEXP * DL],  g_latl[NEXP * DL];
__device__ __half g_W1Th[DH * DL],    g_W1Tl[DH * DL];
__device__ __half g_W2ph[DH * DM],    g_W2pl[DH * DM];
__device__ __half g_WvTh[DM * DH],    g_WvTl[DM * DH];
__device__ __half g_acch[NTOK * DH],  g_accl[NTOK * DH];

__device__ __forceinline__ float gelu_exact(float x) {
    return 0.5f * x * (1.0f + erff(x * 0.70710678118654752440f));
}

// ---------------- fp16x3 helpers ----------------
__device__ __forceinline__ void split2(float x, float y, uint32_t& hi, uint32_t& lo) {
    __half hx = __float2half_rn(x);
    __half hy = __float2half_rn(y);
    float lx = x - __half2float(hx);
    float ly = y - __half2float(hy);
    __half lxh = __float2half_rn(lx);
    __half lyh = __float2half_rn(ly);
    hi = (uint32_t)__half_as_ushort(hx) | ((uint32_t)__half_as_ushort(hy) << 16);
    lo = (uint32_t)__half_as_ushort(lxh) | ((uint32_t)__half_as_ushort(lyh) << 16);
}

__device__ __forceinline__ void hmma(float* d, const uint32_t* a, const uint32_t* b) {
    asm volatile(
        "mma.sync.aligned.m16n8k16.row.col.f32.f16.f16.f32 "
        "{%0,%1,%2,%3},{%4,%5,%6,%7},{%8,%9},{%0,%1,%2,%3};"
        : "+f"(d[0]), "+f"(d[1]), "+f"(d[2]), "+f"(d[3])
        : "r"(a[0]), "r"(a[1]), "r"(a[2]), "r"(a[3]), "r"(b[0]), "r"(b[1]));
}

__device__ __forceinline__ void cp16(uint32_t dst, const void* src) {
    asm volatile("cp.async.cg.shared.global [%0], [%1], 16;" :: "r"(dst), "l"(src));
}
#define CP_COMMIT() asm volatile("cp.async.commit_group;" ::: "memory")
#define CP_WAIT1()  asm volatile("cp.async.wait_group 1;"  ::: "memory")
#define CP_WAIT0()  asm volatile("cp.async.wait_group 0;"  ::: "memory")

// ---------------- pre-split kernels ----------------
__global__ void split_kernel(const float* __restrict__ src, __half* __restrict__ h,
                             __half* __restrict__ l, int n4) {
    int i = blockIdx.x * 256 + threadIdx.x;
    if (i >= n4) return;
    float4 v = ((const float4*)src)[i];
    uint32_t h0, l0, h1, l1;
    split2(v.x, v.y, h0, l0);
    split2(v.z, v.w, h1, l1);
    ((uint2*)h)[i] = make_uint2(h0, h1);
    ((uint2*)l)[i] = make_uint2(l0, l1);
}

__global__ void split_strided_kernel(const float* __restrict__ src,
                                     __half* __restrict__ h, __half* __restrict__ l,
                                     int rows, int cols, int lds) {
    int c4n = cols >> 2;
    int i = blockIdx.x * 256 + threadIdx.x;
    if (i >= rows * c4n) return;
    int r = i / c4n, c = i - r * c4n;
    float4 v = *(const float4*)(src + (size_t)r * lds + c * 4);
    uint32_t h0, l0, h1, l1;
    split2(v.x, v.y, h0, l0);
    split2(v.z, v.w, h1, l1);
    ((uint2*)(h + (size_t)r * cols))[c] = make_uint2(h0, h1);
    ((uint2*)(l + (size_t)r * cols))[c] = make_uint2(l0, l1);
}

// transpose + split: dst[c][r] = src[r][c] as half hi/lo
__global__ void transpose_split_kernel(const float* __restrict__ src,
                                       __half* __restrict__ dh, __half* __restrict__ dl,
                                       int R, int C, int lds) {
    __shared__ float t[32][33];
    int c0 = blockIdx.x * 32, r0 = blockIdx.y * 32;
    #pragma unroll
    for (int i = 0; i < 32; i += 8)
        t[threadIdx.y + i][threadIdx.x] =
            src[(size_t)(r0 + threadIdx.y + i) * lds + c0 + threadIdx.x];
    __syncthreads();
    #pragma unroll
    for (int i = 0; i < 32; i += 8) {
        float v = t[threadIdx.x][threadIdx.y + i];
        __half hh = __float2half_rn(v);
        size_t o = (size_t)(c0 + threadIdx.y + i) * R + r0 + threadIdx.x;
        dh[o] = hh;
        dl[o] = __float2half_rn(v - __half2float(hh));
    }
}

// ---------------- fp16x3 HMMA GEMM, cp.async loader ----------------
// C[M,N] = (Ah+Al)[M,K] * (Bh+Bl)[N,K]^T (+bias | gelu) * scale, fp32 accum,
// dropping the Al*Bl term (~2^-22 relative).
// Block tile 128x128, 8 warps (2x4), warp tile 64x32, K-chunk 32, double buffered.
// SMEM per stage: Ah, Al, Bh, Bl each [128 rows][20 u32] (16 used, 4 pad).
#define HSTR 20
#define MAT_U32 (128 * HSTR)
#define STAGE_U32 (4 * MAT_U32)

__global__ void __launch_bounds__(256, 2)
gemm_h3b(const __half* __restrict__ Ah, const __half* __restrict__ Al,
         const __half* __restrict__ Bh, const __half* __restrict__ Bl,
         float* __restrict__ C, const float* __restrict__ bias,
         int K, int lda, int ldb, int ldc, int epi, float scale) {
    extern __shared__ uint32_t smu[];
    uint32_t smaddr = (uint32_t)__cvta_generic_to_shared(smu);

    int tid = threadIdx.x;
    int lane = tid & 31;
    int wid = tid >> 5;
    int wm = (wid >> 2) * 64;     // 0 or 64
    int wn = (wid & 3) * 32;      // 0,32,64,96
    int g = lane >> 2, tg = lane & 3;

    int m0 = blockIdx.y * 128, n0 = blockIdx.x * 128;

    float acc[4][4][4];
    #pragma unroll
    for (int mi = 0; mi < 4; mi++)
        #pragma unroll
        for (int ni = 0; ni < 4; ni++)
            #pragma unroll
            for (int t = 0; t < 4; t++) acc[mi][ni][t] = 0.0f;

    // per-thread chunk coords: 2048 16B-chunks per stage, 8 per thread.
    // i-th chunk: mat = i>>1 (Ah,Al,Bh,Bl), row = (tid + 256*(i&1))>>2, q = tid&3.
    int qk = tid & 3;

    // s is the SMEM stage buffer index (0 or 1); k0 the K offset.
    auto issue = [&](int s, int k0) {
        uint32_t base = smaddr + (uint32_t)(s * STAGE_U32) * 4;
        #pragma unroll
        for (int i = 0; i < 8; i++) {
            int mat = i >> 1;
            int r = (tid + 256 * (i & 1)) >> 2;
            const __half* gp;
            if (mat == 0)      gp = Ah + (size_t)(m0 + r) * lda + k0 + qk * 8;
            else if (mat == 1) gp = Al + (size_t)(m0 + r) * lda + k0 + qk * 8;
            else if (mat == 2) gp = Bh + (size_t)(n0 + r) * ldb + k0 + qk * 8;
            else               gp = Bl + (size_t)(n0 + r) * ldb + k0 + qk * 8;
            cp16(base + (uint32_t)(mat * MAT_U32 + r * HSTR + qk * 4) * 4, gp);
        }
    };

    int nkt = K >> 5;
    issue(0, 0);
    CP_COMMIT();
    if (nkt > 1) { issue(1, 32); CP_COMMIT(); CP_WAIT1(); }
    else { CP_WAIT0(); }
    __syncthreads();

    for (int kt = 0; kt < nkt; kt++) {
        int cur = kt & 1;
        const uint32_t* st = smu + cur * STAGE_U32;

        #pragma unroll
        for (int ks = 0; ks < 2; ks++) {          // two K16 steps per chunk
            int kc = ks * 8;
            uint32_t ah[4][4], al[4][4], bh[4][2], bl[4][2];
            #pragma unroll
            for (int mi = 0; mi < 4; mi++) {
                int r = wm + mi * 16 + g;
                ah[mi][0] = st[r * HSTR + kc + tg];
                ah[mi][1] = st[(r + 8) * HSTR + kc + tg];
                ah[mi][2] = st[r * HSTR + kc + tg + 4];
                ah[mi][3] = st[(r + 8) * HSTR + kc + tg + 4];
                al[mi][0] = st[MAT_U32 + r * HSTR + kc + tg];
                al[mi][1] = st[MAT_U32 + (r + 8) * HSTR + kc + tg];
                al[mi][2] = st[MAT_U32 + r * HSTR + kc + tg + 4];
                al[mi][3] = st[MAT_U32 + (r + 8) * HSTR + kc + tg + 4];
            }
            #pragma unroll
            for (int ni = 0; ni < 4; ni++) {
                int rn = wn + ni * 8 + g;
                bh[ni][0] = st[2 * MAT_U32 + rn * HSTR + kc + tg];
                bh[ni][1] = st[2 * MAT_U32 + rn * HSTR + kc + tg + 4];
                bl[ni][0] = st[3 * MAT_U32 + rn * HSTR + kc + tg];
                bl[ni][1] = st[3 * MAT_U32 + rn * HSTR + kc + tg + 4];
            }
            #pragma unroll
            for (int mi = 0; mi < 4; mi++)
                #pragma unroll
                for (int ni = 0; ni < 4; ni++) {
                    hmma(acc[mi][ni], ah[mi], bh[ni]);
                    hmma(acc[mi][ni], al[mi], bh[ni]);
                    hmma(acc[mi][ni], ah[mi], bl[ni]);
                }
        }

        if (kt + 1 < nkt) {
            __syncthreads();                       // done reading buf cur
            if (kt + 2 < nkt) {
                issue((kt + 2) & 1, (kt + 2) * 32);   // FIX: stage buffer index, not kt+2
                CP_COMMIT();
                CP_WAIT1();
            } else {
                CP_WAIT0();
            }
            __syncthreads();                       // stage kt+1 visible
        }
    }

    // ---- epilogue ----
    #pragma unroll
    for (int mi = 0; mi < 4; mi++) {
        #pragma unroll
        for (int h2 = 0; h2 < 2; h2++) {
            size_t row = (size_t)(m0 + wm + mi * 16 + g + h2 * 8);
            #pragma unroll
            for (int ni = 0; ni < 4; ni++) {
                int c = n0 + wn + ni * 8 + 2 * tg;
                float v0 = acc[mi][ni][2 * h2];
                float v1 = acc[mi][ni][2 * h2 + 1];
                if (epi == 1) { v0 += bias[c]; v1 += bias[c + 1]; }
                else if (epi == 2) { v0 = gelu_exact(v0); v1 = gelu_exact(v1); }
                v0 *= scale; v1 *= scale;
                *(float2*)(C + row * ldc + c) = make_float2(v0, v1);
            }
        }
    }
}

// ---------------- tiny utility kernels ----------------
__global__ void zero_stats_kernel() {
    int i = threadIdx.x;
    g_sum[i] = 0.0f;
    g_sqs[i] = 0.0f;
}

__global__ void bn_reduce_kernel() {
    int tid = threadIdx.x;             // 256
    int r0 = blockIdx.x * 64;          // 128 blocks
    float s0 = 0.f, s1 = 0.f, s2 = 0.f, s3 = 0.f;
    float q0 = 0.f, q1 = 0.f, q2 = 0.f, q3 = 0.f;
    for (int r = 0; r < 64; r++) {
        const float* row = g_q + (size_t)(r0 + r) * 1024;
        float v0 = row[tid];
        float v1 = row[tid + 256];
        float v2 = row[tid + 512];
        float v3 = row[tid + 768];
        s0 += v0; q0 += v0 * v0;
        s1 += v1; q1 += v1 * v1;
        s2 += v2; q2 += v2 * v2;
        s3 += v3; q3 += v3 * v3;
    }
    atomicAdd(&g_sum[tid],       s0);
    atomicAdd(&g_sum[tid + 256], s1);
    atomicAdd(&g_sum[tid + 512], s2);
    atomicAdd(&g_sum[tid + 768], s3);
    atomicAdd(&g_sqs[tid],       q0);
    atomicAdd(&g_sqs[tid + 256], q1);
    atomicAdd(&g_sqs[tid + 512], q2);
    atomicAdd(&g_sqs[tid + 768], q3);
}

__global__ void bn_finalize_kernel(const float* __restrict__ gamma,
                                   const float* __restrict__ beta) {
    int c = threadIdx.x;  // 1024
    float mean = g_sum[c] * (1.0f / NTOK);
    float var  = g_sqs[c] * (1.0f / NTOK) - mean * mean;
    float rstd = rsqrtf(var + BN_EPS);
    float a = gamma[c] * rstd;
    g_a[c] = a;
    g_b[c] = beta[c] - mean * a;
}

__global__ void fold_sk_kernel(const float* __restrict__ sk1,
                               const float* __restrict__ sk2) {
    int h = blockIdx.x >> 7;      // 512 blocks
    int k = blockIdx.x & 127;
    int j = threadIdx.x;          // 128
    float w1 = sk1[k * 128 + j];
    float w2 = sk2[k * 128 + j];
    float a1 = g_a[h * 256 + j],       b1 = g_b[h * 256 + j];
    float a2 = g_a[h * 256 + 128 + j], b2 = g_b[h * 256 + 128 + j];
    g_sk1a[(h * 128 + k) * 128 + j] = w1 * a1;
    g_sk2a[(h * 128 + k) * 128 + j] = w2 * a2;
    float p1 = w1 * b1, p2 = w2 * b2;
    const unsigned FULL = 0xffffffffu;
    #pragma unroll
    for (int off = 16; off > 0; off >>= 1) {
        p1 += __shfl_down_sync(FULL, p1, off);
        p2 += __shfl_down_sync(FULL, p2, off);
    }
    __shared__ float sh[8];
    int w = j >> 5, l = j & 31;
    if (l == 0) { sh[w] = p1; sh[4 + w] = p2; }
    __syncthreads();
    if (j == 0) {
        g_bs1[h * 128 + k] = sh[0] + sh[1] + sh[2] + sh[3];
        g_bs2[h * 128 + k] = sh[4] + sh[5] + sh[6] + sh[7];
    }
}

// ---------------- FFMA SGEMM (s1/s2 — selection-path numerics preserved) ----------------
__global__ void __launch_bounds__(256)
sgemm128(const float* __restrict__ A, const float* __restrict__ B,
         float* __restrict__ C, const float* __restrict__ bias,
         int K, int lda, int ldb, int ldc,
         long long aS, long long bS, long long cS, long long biasS,
         int transB, int epi, float scale) {
    A += (long long)blockIdx.z * aS;
    B += (long long)blockIdx.z * bS;
    C += (long long)blockIdx.z * cS;
    const float* biasz = bias ? (bias + (long long)blockIdx.z * biasS) : nullptr;

    __shared__ __align__(16) float As[2][8][128];
    __shared__ __align__(16) float Bs[2][8][128];

    int tid = threadIdx.x;
    int m0 = blockIdx.y * 128, n0 = blockIdx.x * 128;
    int tx = tid & 15, ty = tid >> 4;

    float acc[8][8];
    #pragma unroll
    for (int i = 0; i < 8; i++)
        #pragma unroll
        for (int j = 0; j < 8; j++) acc[i][j] = 0.0f;

    int hr = tid >> 1, hk = (tid & 1) * 4;
    int br = tid >> 5, bc = (tid & 31) * 4;

    const float* Aptr = A + (long long)(m0 + hr) * lda + hk;
    const float* Bptr;
    long long bstep;
    if (transB) { Bptr = B + (long long)(n0 + hr) * ldb + hk; bstep = 8; }
    else        { Bptr = B + (long long)br * ldb + n0 + bc;   bstep = 8LL * ldb; }

    float4 av = *(const float4*)Aptr;
    float4 bv = *(const float4*)Bptr;
    As[0][hk + 0][hr] = av.x; As[0][hk + 1][hr] = av.y;
    As[0][hk + 2][hr] = av.z; As[0][hk + 3][hr] = av.w;
    if (transB) {
        Bs[0][hk + 0][hr] = bv.x; Bs[0][hk + 1][hr] = bv.y;
        Bs[0][hk + 2][hr] = bv.z; Bs[0][hk + 3][hr] = bv.w;
    } else {
        *(float4*)&Bs[0][br][bc] = bv;
    }
    __syncthreads();

    int nk = K >> 3;
    for (int kt = 0; kt < nk; kt++) {
        int cur = kt & 1;
        bool more = (kt + 1 < nk);
        if (more) {
            av = *(const float4*)(Aptr + (long long)(kt + 1) * 8);
            bv = *(const float4*)(Bptr + (long long)(kt + 1) * bstep);
        }
        #pragma unroll
        for (int kk = 0; kk < 8; kk++) {
            float4 a0 = *(const float4*)&As[cur][kk][ty * 4];
            float4 a1 = *(const float4*)&As[cur][kk][ty * 4 + 64];
            float4 b0 = *(const float4*)&Bs[cur][kk][tx * 4];
            float4 b1 = *(const float4*)&Bs[cur][kk][tx * 4 + 64];
            float a[8] = {a0.x, a0.y, a0.z, a0.w, a1.x, a1.y, a1.z, a1.w};
            float b[8] = {b0.x, b0.y, b0.z, b0.w, b1.x, b1.y, b1.z, b1.w};
            #pragma unroll
            for (int i = 0; i < 8; i++)
                #pragma unroll
                for (int j = 0; j < 8; j++)
                    acc[i][j] = fmaf(a[i], b[j], acc[i][j]);
        }
        if (more) {
            int nxt = cur ^ 1;
            As[nxt][hk + 0][hr] = av.x; As[nxt][hk + 1][hr] = av.y;
            As[nxt][hk + 2][hr] = av.z; As[nxt][hk + 3][hr] = av.w;
            if (transB) {
                Bs[nxt][hk + 0][hr] = bv.x; Bs[nxt][hk + 1][hr] = bv.y;
                Bs[nxt][hk + 2][hr] = bv.z; Bs[nxt][hk + 3][hr] = bv.w;
            } else {
                *(float4*)&Bs[nxt][br][bc] = bv;
            }
            __syncthreads();
        }
    }

    #pragma unroll
    for (int i = 0; i < 8; i++) {
        long long row = m0 + ty * 4 + (i & 3) + (i >> 2) * 64;
        #pragma unroll
        for (int jh = 0; jh < 2; jh++) {
            int col = n0 + tx * 4 + jh * 64;
            float4 v;
            float* vp = &v.x;
            #pragma unroll
            for (int j = 0; j < 4; j++) {
                float t = acc[i][jh * 4 + j];
                if (epi == 1) t += biasz[col + j];
                else if (epi == 2) t = gelu_exact(t);
                vp[j] = t * scale;
            }
            *(float4*)(C + row * ldc + col) = v;
        }
    }
}

// ---------------- top-k machinery: one warp per (n,h) ----------------
__global__ void __launch_bounds__(256) topk_kernel() {
    const unsigned FULL = 0xffffffffu;
    int gw = (blockIdx.x * 256 + threadIdx.x) >> 5;   // 0..32767
    int lane = threadIdx.x & 31;
    const float* p1 = g_s1 + (size_t)gw * 128;
    const float* p2 = g_s2 + (size_t)gw * 128;

    float v1[4], v2[4];
    #pragma unroll
    for (int i = 0; i < 4; i++) {
        v1[i] = p1[lane + 32 * i];
        v2[i] = p2[lane + 32 * i];
    }

    float slot_v1 = 0.f, slot_v2 = 0.f;
    int   slot_i1 = 0,   slot_i2 = 0;
    #pragma unroll
    for (int t = 0; t < 16; t++) {
        {
            float bv = v1[0]; int bi = lane;
            #pragma unroll
            for (int i = 1; i < 4; i++)
                if (v1[i] > bv) { bv = v1[i]; bi = lane + 32 * i; }
            #pragma unroll
            for (int off = 16; off > 0; off >>= 1) {
                float ov = __shfl_down_sync(FULL, bv, off);
                int   oi = __shfl_down_sync(FULL, bi, off);
                if (ov > bv || (ov == bv && oi < bi)) { bv = ov; bi = oi; }
            }
            bv = __shfl_sync(FULL, bv, 0);
            bi = __shfl_sync(FULL, bi, 0);
            if (lane == t) { slot_v1 = bv; slot_i1 = bi; }
            int sl = bi >> 5, ol = bi & 31;
            if (lane == ol) {
                if      (sl == 0) v1[0] = -3.4e38f;
                else if (sl == 1) v1[1] = -3.4e38f;
                else if (sl == 2) v1[2] = -3.4e38f;
                else              v1[3] = -3.4e38f;
            }
        }
        {
            float bv = v2[0]; int bi = lane;
            #pragma unroll
            for (int i = 1; i < 4; i++)
                if (v2[i] > bv) { bv = v2[i]; bi = lane + 32 * i; }
            #pragma unroll
            for (int off = 16; off > 0; off >>= 1) {
                float ov = __shfl_down_sync(FULL, bv, off);
                int   oi = __shfl_down_sync(FULL, bi, off);
                if (ov > bv || (ov == bv && oi < bi)) { bv = ov; bi = oi; }
            }
            bv = __shfl_sync(FULL, bv, 0);
            bi = __shfl_sync(FULL, bi, 0);
            if (lane == t) { slot_v2 = bv; slot_i2 = bi; }
            int sl = bi >> 5, ol = bi & 31;
            if (lane == ol) {
                if      (sl == 0) v2[0] = -3.4e38f;
                else if (sl == 1) v2[1] = -3.4e38f;
                else if (sl == 2) v2[2] = -3.4e38f;
                else              v2[3] = -3.4e38f;
            }
        }
    }

    float cv[8];
    #pragma unroll
    for (int j = 0; j < 8; j++) {
        int c = lane + 32 * j;
        float a = __shfl_sync(FULL, slot_v1, c >> 4);
        float b = __shfl_sync(FULL, slot_v2, c & 15);
        cv[j] = a + b;
    }

    float sel_v = -3.4e38f; int sel_c = 0;
    #pragma unroll
    for (int t = 0; t < 8; t++) {
        float bv = cv[0]; int bc = lane;
        #pragma unroll
        for (int j = 1; j < 8; j++)
            if (cv[j] > bv) { bv = cv[j]; bc = lane + 32 * j; }
        #pragma unroll
        for (int off = 16; off > 0; off >>= 1) {
            float ov = __shfl_down_sync(FULL, bv, off);
            int   oc = __shfl_down_sync(FULL, bc, off);
            if (ov > bv || (ov == bv && oc < bc)) { bv = ov; bc = oc; }
        }
        bv = __shfl_sync(FULL, bv, 0);
        bc = __shfl_sync(FULL, bc, 0);
        if (lane == t) { sel_v = bv; sel_c = bc; }
        int sl = bc >> 5, ol = bc & 31;
        if (lane == ol) {
            switch (sl) {
                case 0: cv[0] = -3.4e38f; break;
                case 1: cv[1] = -3.4e38f; break;
                case 2: cv[2] = -3.4e38f; break;
                case 3: cv[3] = -3.4e38f; break;
                case 4: cv[4] = -3.4e38f; break;
                case 5: cv[5] = -3.4e38f; break;
                case 6: cv[6] = -3.4e38f; break;
                default: cv[7] = -3.4e38f; break;
            }
        }
    }

    float mv = (lane < 8) ? sel_v : -3.4e38f;
    #pragma unroll
    for (int off = 4; off > 0; off >>= 1)
        mv = fmaxf(mv, __shfl_xor_sync(FULL, mv, off));
    float ev = (lane < 8) ? expf(sel_v - mv) : 0.0f;
    float sum = ev;
    #pragma unroll
    for (int off = 4; off > 0; off >>= 1)
        sum += __shfl_xor_sync(FULL, sum, off);
    float p = ev / sum;

    int i1 = __shfl_sync(FULL, slot_i1, sel_c >> 4);
    int i2 = __shfl_sync(FULL, slot_i2, sel_c & 15);
    if (lane < 8) {
        g_probs[(size_t)gw * 8 + lane] = p;
        g_eidx [(size_t)gw * 8 + lane] = i1 * NSUB + i2;
    }
}

// ---------------- expert gather + dot + gelu + weighted accumulate ----------------
__global__ void __launch_bounds__(256) gather_kernel() {
    const unsigned FULL = 0xffffffffu;
    __shared__ float sx[DH];
    __shared__ float sacc[8][DH];
    int n = blockIdx.x;
    int tid = threadIdx.x;
    int w = tid >> 5, lane = tid & 31;

    sx[tid]       = g_xp[(size_t)n * DH + tid];
    sx[tid + 256] = g_xp[(size_t)n * DH + tid + 256];
    #pragma unroll
    for (int i = 0; i < 16; i++) sacc[w][lane + 32 * i] = 0.0f;
    __syncthreads();

    #pragma unroll
    for (int p = 0; p < 4; p++) {
        int idx = w * 4 + p;
        int e = g_eidx[(size_t)n * 32 + idx];
        float prob = g_probs[(size_t)n * 32 + idx];
        const float* hrow = g_H + (size_t)e * DH;
        float hv[16];
        float dot = 0.0f;
        #pragma unroll
        for (int i = 0; i < 16; i++) {
            hv[i] = hrow[lane + 32 * i];
            dot = fmaf(hv[i], sx[lane + 32 * i], dot);
        }
        #pragma unroll
        for (int off = 16; off > 0; off >>= 1)
            dot += __shfl_down_sync(FULL, dot, off);
        dot = __shfl_sync(FULL, dot, 0);
        float act = gelu_exact(dot) * prob;
        #pragma unroll
        for (int i = 0; i < 16; i++)
            sacc[w][lane + 32 * i] = fmaf(act, hv[i], sacc[w][lane + 32 * i]);
    }
    __syncthreads();

    for (int c = tid; c < DH; c += 256) {
        float s = 0.0f;
        #pragma unroll
        for (int ww = 0; ww < 8; ww++) s += sacc[ww][c];
        g_acc[(size_t)n * DH + c] = s;
    }
}

// ---------------- host launcher ----------------
extern "C" void kernel_launch(void* const* d_in, const int* in_sizes, int n_in,
                              void* d_out, int out_size) {
    (void)in_sizes; (void)n_in; (void)out_size;
    const float* x    = (const float*)d_in[0];
    const float* Wq   = (const float*)d_in[1];
    const float* bq   = (const float*)d_in[2];
    const float* gam  = (const float*)d_in[3];
    const float* bet  = (const float*)d_in[4];
    const float* sk1  = (const float*)d_in[5];
    const float* sk2  = (const float*)d_in[6];
    const float* lat  = (const float*)d_in[7];
    const float* W1   = (const float*)d_in[8];
    const float* W2   = (const float*)d_in[9];
    float* out = (float*)d_out;

    float *q, *bs1, *bs2, *s1, *s2, *sk1a, *sk2a, *H, *xp, *acc;
    cudaGetSymbolAddress((void**)&q,    g_q);
    cudaGetSymbolAddress((void**)&sk1a, g_sk1a);
    cudaGetSymbolAddress((void**)&sk2a, g_sk2a);
    cudaGetSymbolAddress((void**)&bs1,  g_bs1);
    cudaGetSymbolAddress((void**)&bs2,  g_bs2);
    cudaGetSymbolAddress((void**)&s1,   g_s1);
    cudaGetSymbolAddress((void**)&s2,   g_s2);
    cudaGetSymbolAddress((void**)&H,    g_H);
    cudaGetSymbolAddress((void**)&xp,   g_xp);
    cudaGetSymbolAddress((void**)&acc,  g_acc);

    __half *xh, *xl, *Wqh, *Wql, *lath, *latl, *W1Th, *W1Tl, *W2ph, *W2pl,
           *WvTh, *WvTl, *acch, *accl;
    cudaGetSymbolAddress((void**)&xh,   g_xh);
    cudaGetSymbolAddress((void**)&xl,   g_xl);
    cudaGetSymbolAddress((void**)&Wqh,  g_Wqh);
    cudaGetSymbolAddress((void**)&Wql,  g_Wql);
    cudaGetSymbolAddress((void**)&lath, g_lath);
    cudaGetSymbolAddress((void**)&latl, g_latl);
    cudaGetSymbolAddress((void**)&W1Th, g_W1Th);
    cudaGetSymbolAddress((void**)&W1Tl, g_W1Tl);
    cudaGetSymbolAddress((void**)&W2ph, g_W2ph);
    cudaGetSymbolAddress((void**)&W2pl, g_W2pl);
    cudaGetSymbolAddress((void**)&WvTh, g_WvTh);
    cudaGetSymbolAddress((void**)&WvTl, g_WvTl);
    cudaGetSymbolAddress((void**)&acch, g_acch);
    cudaGetSymbolAddress((void**)&accl, g_accl);

    const int h3_smem = 2 * STAGE_U32 * 4;   // 81920 bytes
    cudaFuncSetAttribute(gemm_h3b, cudaFuncAttributeMaxDynamicSharedMemorySize, h3_smem);

    // 1. pre-split operands to half hi/lo + zero BN stats
    zero_stats_kernel<<<1, 1024>>>();
    split_kernel<<<8192, 256>>>(x,   xh,   xl,   NTOK * DM / 4);
    split_kernel<<<1024, 256>>>(Wq,  Wqh,  Wql,  1024 * 1024 / 4);
    split_kernel<<<4096, 256>>>(lat, lath, latl, NEXP * DL / 4);
    transpose_split_kernel<<<dim3(16, 8),  dim3(32, 8)>>>(W1, W1Th, W1Tl, 256, 512, 512);
    transpose_split_kernel<<<dim3(32, 16), dim3(32, 8)>>>(W2 + 1024, WvTh, WvTl, 512, 1024, 2048);
    split_strided_kernel<<<512, 256>>>(W2, W2ph, W2pl, 512, 1024, 2048);

    // 2. q = x @ Wq^T + bq   [8192,1024]x[1024,1024]^T   (fp16x3 HMMA)
    gemm_h3b<<<dim3(8, 64), 256, h3_smem>>>(xh, xl, Wqh, Wql, q, bq,
                                            1024, 1024, 1024, 1024, 1, 1.0f);

    // 3-5. BN stats, fold into affine, fold affine into score weights
    bn_reduce_kernel<<<128, 256>>>();
    bn_finalize_kernel<<<1, 1024>>>(gam, bet);
    fold_sk_kernel<<<512, 128>>>(sk1, sk2);

    // 6-7. s1, s2 (FFMA — selection-path numerics preserved)
    sgemm128<<<dim3(1, 64, 4), 256>>>(q, sk1a, s1, bs1,
                                      128, 1024, 128, 512,
                                      256, 128 * 128, 128, 128, 1, 1, 1.0f);
    sgemm128<<<dim3(1, 64, 4), 256>>>(q + 128, sk2a, s2, bs2,
                                      128, 1024, 128, 512,
                                      256, 128 * 128, 128, 128, 1, 1, 1.0f);

    // 8. top-16 x top-16 -> top-8, softmax, expert indices
    topk_kernel<<<4096, 256>>>();

    // 9. H = gelu(latents @ W1)   [16384,256]x[512,256]^T   (fp16x3 HMMA)
    gemm_h3b<<<dim3(4, 128), 256, h3_smem>>>(lath, latl, W1Th, W1Tl, H, nullptr,
                                             256, 256, 256, 512, 2, 1.0f);

    // 10. x_proj = x @ W2[:, :1024]^T   [8192,1024]x[512,1024]^T (fp16x3 HMMA)
    gemm_h3b<<<dim3(4, 64), 256, h3_smem>>>(xh, xl, W2ph, W2pl, xp, nullptr,
                                            1024, 1024, 1024, 512, 0, 1.0f);

    // 11. gather experts, act = gelu(<hg, x_proj>)*prob, acc = sum act*hg
    gather_kernel<<<NTOK, 256>>>();

    // 12. split acc, then out = acc @ Wv / NUM_HEADS  (fp16x3 HMMA)
    split_kernel<<<4096, 256>>>(acc, acch, accl, NTOK * DH / 4);
    gemm_h3b<<<dim3(8, 64), 256, h3_smem>>>(acch, accl, WvTh, WvTl, out, nullptr,
                                            512, 512, 512, 1024, 0, 0.25f);
}

// round 15
// speedup vs baseline: 1.8563x; 1.0242x over previous
#include <cuda_runtime.h>
#include <cuda_fp16.h>
#include <math.h>
#include <stdint.h>

#define NTOK   8192
#define DM     1024
#define NH     4
#define DQ     256
#define NSUB   128
#define TK     8
#define DL     256
#define DH     512
#define NEXP   16384
#define BN_EPS 1e-5f
#define SOFF   (NTOK * 512)   // offset of s2 region inside g_s

// ---------------- scratch (static __device__: allocation-free) ----------------
__device__ float g_q[NTOK * 1024];          // 32 MB (fp32 q for BN stats)
__device__ float g_sum[1024];
__device__ float g_sqs[1024];
__device__ float g_a[1024];
__device__ float g_b[1024];
__device__ float g_s[2 * NTOK * NH * 128];  // 32 MB: s1 region then s2 region
__device__ float g_bs[8 * 128];             // folded score bias, slot z = (is2*4+h)
__device__ float g_probs[NTOK * NH * TK];
__device__ int   g_eidx[NTOK * NH * TK];
__device__ float g_H[NEXP * DH];            // 32 MB
__device__ float g_xp[NTOK * DH];           // 16 MB

// pre-split half hi/lo operand buffers
__device__ __half g_xh[NTOK * DM],   g_xl[NTOK * DM];
__device__ __half g_qh[NTOK * DM],   g_ql[NTOK * DM];      // q splits (GEMM epilogue)
__device__ __half g_Wqh[1024 * 1024], g_Wql[1024 * 1024];
__device__ __half g_lath[NEXP * DL],  g_latl[NEXP * DL];
__device__ __half g_W1Th[DH * DL],    g_W1Tl[DH * DL];
__device__ __half g_W2ph[DH * DM],    g_W2pl[DH * DM];
__device__ __half g_WvTh[DM * DH],    g_WvTl[DM * DH];
__device__ __half g_acch[NTOK * DH],  g_accl[NTOK * DH];
__device__ __half g_skh[8 * 128 * 128], g_skl[8 * 128 * 128]; // folded sk, hi/lo

__device__ __forceinline__ float gelu_exact(float x) {
    return 0.5f * x * (1.0f + erff(x * 0.70710678118654752440f));
}

// ---------------- fp16x3 helpers ----------------
__device__ __forceinline__ void split2(float x, float y, uint32_t& hi, uint32_t& lo) {
    __half hx = __float2half_rn(x);
    __half hy = __float2half_rn(y);
    float lx = x - __half2float(hx);
    float ly = y - __half2float(hy);
    __half lxh = __float2half_rn(lx);
    __half lyh = __float2half_rn(ly);
    hi = (uint32_t)__half_as_ushort(hx) | ((uint32_t)__half_as_ushort(hy) << 16);
    lo = (uint32_t)__half_as_ushort(lxh) | ((uint32_t)__half_as_ushort(lyh) << 16);
}

__device__ __forceinline__ void hmma(float* d, const uint32_t* a, const uint32_t* b) {
    asm volatile(
        "mma.sync.aligned.m16n8k16.row.col.f32.f16.f16.f32 "
        "{%0,%1,%2,%3},{%4,%5,%6,%7},{%8,%9},{%0,%1,%2,%3};"
        : "+f"(d[0]), "+f"(d[1]), "+f"(d[2]), "+f"(d[3])
        : "r"(a[0]), "r"(a[1]), "r"(a[2]), "r"(a[3]), "r"(b[0]), "r"(b[1]));
}

__device__ __forceinline__ void cp16(uint32_t dst, const void* src) {
    asm volatile("cp.async.cg.shared.global [%0], [%1], 16;" :: "r"(dst), "l"(src));
}
#define CP_COMMIT() asm volatile("cp.async.commit_group;" ::: "memory")
#define CP_WAIT1()  asm volatile("cp.async.wait_group 1;"  ::: "memory")
#define CP_WAIT0()  asm volatile("cp.async.wait_group 0;"  ::: "memory")

// ---------------- pre-split kernels ----------------
__global__ void split_kernel(const float* __restrict__ src, __half* __restrict__ h,
                             __half* __restrict__ l, int n4) {
    int i = blockIdx.x * 256 + threadIdx.x;
    if (i >= n4) return;
    float4 v = ((const float4*)src)[i];
    uint32_t h0, l0, h1, l1;
    split2(v.x, v.y, h0, l0);
    split2(v.z, v.w, h1, l1);
    ((uint2*)h)[i] = make_uint2(h0, h1);
    ((uint2*)l)[i] = make_uint2(l0, l1);
}

__global__ void split_strided_kernel(const float* __restrict__ src,
                                     __half* __restrict__ h, __half* __restrict__ l,
                                     int rows, int cols, int lds) {
    int c4n = cols >> 2;
    int i = blockIdx.x * 256 + threadIdx.x;
    if (i >= rows * c4n) return;
    int r = i / c4n, c = i - r * c4n;
    float4 v = *(const float4*)(src + (size_t)r * lds + c * 4);
    uint32_t h0, l0, h1, l1;
    split2(v.x, v.y, h0, l0);
    split2(v.z, v.w, h1, l1);
    ((uint2*)(h + (size_t)r * cols))[c] = make_uint2(h0, h1);
    ((uint2*)(l + (size_t)r * cols))[c] = make_uint2(l0, l1);
}

// transpose + split: dst[c][r] = src[r][c] as half hi/lo
__global__ void transpose_split_kernel(const float* __restrict__ src,
                                       __half* __restrict__ dh, __half* __restrict__ dl,
                                       int R, int C, int lds) {
    __shared__ float t[32][33];
    int c0 = blockIdx.x * 32, r0 = blockIdx.y * 32;
    #pragma unroll
    for (int i = 0; i < 32; i += 8)
        t[threadIdx.y + i][threadIdx.x] =
            src[(size_t)(r0 + threadIdx.y + i) * lds + c0 + threadIdx.x];
    __syncthreads();
    #pragma unroll
    for (int i = 0; i < 32; i += 8) {
        float v = t[threadIdx.x][threadIdx.y + i];
        __half hh = __float2half_rn(v);
        size_t o = (size_t)(c0 + threadIdx.y + i) * R + r0 + threadIdx.x;
        dh[o] = hh;
        dl[o] = __float2half_rn(v - __half2float(hh));
    }
}

// ---------------- fp16x3 HMMA GEMM, cp.async loader ----------------
// C[M,N] = (Ah+Al)[M,K] * (Bh+Bl)[N,K]^T (+bias | gelu) * scale, fp32 accum.
// Block tile 128x128, 8 warps, warp tile 64x32, K-chunk 32, double buffered.
// If Ch != nullptr, the epilogue also writes half hi/lo splits of C.
#define HSTR 20
#define MAT_U32 (128 * HSTR)
#define STAGE_U32 (4 * MAT_U32)

__global__ void __launch_bounds__(256, 2)
gemm_h3b(const __half* __restrict__ Ah, const __half* __restrict__ Al,
         const __half* __restrict__ Bh, const __half* __restrict__ Bl,
         float* __restrict__ C, const float* __restrict__ bias,
         int K, int lda, int ldb, int ldc, int epi, float scale,
         __half* __restrict__ Ch, __half* __restrict__ Cl) {
    extern __shared__ uint32_t smu[];
    uint32_t smaddr = (uint32_t)__cvta_generic_to_shared(smu);

    int tid = threadIdx.x;
    int lane = tid & 31;
    int wid = tid >> 5;
    int wm = (wid >> 2) * 64;
    int wn = (wid & 3) * 32;
    int g = lane >> 2, tg = lane & 3;

    int m0 = blockIdx.y * 128, n0 = blockIdx.x * 128;

    float acc[4][4][4];
    #pragma unroll
    for (int mi = 0; mi < 4; mi++)
        #pragma unroll
        for (int ni = 0; ni < 4; ni++)
            #pragma unroll
            for (int t = 0; t < 4; t++) acc[mi][ni][t] = 0.0f;

    int qk = tid & 3;

    auto issue = [&](int s, int k0) {
        uint32_t base = smaddr + (uint32_t)(s * STAGE_U32) * 4;
        #pragma unroll
        for (int i = 0; i < 8; i++) {
            int mat = i >> 1;
            int r = (tid + 256 * (i & 1)) >> 2;
            const __half* gp;
            if (mat == 0)      gp = Ah + (size_t)(m0 + r) * lda + k0 + qk * 8;
            else if (mat == 1) gp = Al + (size_t)(m0 + r) * lda + k0 + qk * 8;
            else if (mat == 2) gp = Bh + (size_t)(n0 + r) * ldb + k0 + qk * 8;
            else               gp = Bl + (size_t)(n0 + r) * ldb + k0 + qk * 8;
            cp16(base + (uint32_t)(mat * MAT_U32 + r * HSTR + qk * 4) * 4, gp);
        }
    };

    int nkt = K >> 5;
    issue(0, 0);
    CP_COMMIT();
    if (nkt > 1) { issue(1, 32); CP_COMMIT(); CP_WAIT1(); }
    else { CP_WAIT0(); }
    __syncthreads();

    for (int kt = 0; kt < nkt; kt++) {
        int cur = kt & 1;
        const uint32_t* st = smu + cur * STAGE_U32;

        #pragma unroll
        for (int ks = 0; ks < 2; ks++) {
            int kc = ks * 8;
            uint32_t ah[4][4], al[4][4], bh[4][2], bl[4][2];
            #pragma unroll
            for (int mi = 0; mi < 4; mi++) {
                int r = wm + mi * 16 + g;
                ah[mi][0] = st[r * HSTR + kc + tg];
                ah[mi][1] = st[(r + 8) * HSTR + kc + tg];
                ah[mi][2] = st[r * HSTR + kc + tg + 4];
                ah[mi][3] = st[(r + 8) * HSTR + kc + tg + 4];
                al[mi][0] = st[MAT_U32 + r * HSTR + kc + tg];
                al[mi][1] = st[MAT_U32 + (r + 8) * HSTR + kc + tg];
                al[mi][2] = st[MAT_U32 + r * HSTR + kc + tg + 4];
                al[mi][3] = st[MAT_U32 + (r + 8) * HSTR + kc + tg + 4];
            }
            #pragma unroll
            for (int ni = 0; ni < 4; ni++) {
                int rn = wn + ni * 8 + g;
                bh[ni][0] = st[2 * MAT_U32 + rn * HSTR + kc + tg];
                bh[ni][1] = st[2 * MAT_U32 + rn * HSTR + kc + tg + 4];
                bl[ni][0] = st[3 * MAT_U32 + rn * HSTR + kc + tg];
                bl[ni][1] = st[3 * MAT_U32 + rn * HSTR + kc + tg + 4];
            }
            #pragma unroll
            for (int mi = 0; mi < 4; mi++)
                #pragma unroll
                for (int ni = 0; ni < 4; ni++) {
                    hmma(acc[mi][ni], ah[mi], bh[ni]);
                    hmma(acc[mi][ni], al[mi], bh[ni]);
                    hmma(acc[mi][ni], ah[mi], bl[ni]);
                }
        }

        if (kt + 1 < nkt) {
            __syncthreads();
            if (kt + 2 < nkt) {
                issue((kt + 2) & 1, (kt + 2) * 32);
                CP_COMMIT();
                CP_WAIT1();
            } else {
                CP_WAIT0();
            }
            __syncthreads();
        }
    }

    // ---- epilogue (optionally also writes half hi/lo splits) ----
    #pragma unroll
    for (int mi = 0; mi < 4; mi++) {
        #pragma unroll
        for (int h2 = 0; h2 < 2; h2++) {
            size_t row = (size_t)(m0 + wm + mi * 16 + g + h2 * 8);
            #pragma unroll
            for (int ni = 0; ni < 4; ni++) {
                int c = n0 + wn + ni * 8 + 2 * tg;
                float v0 = acc[mi][ni][2 * h2];
                float v1 = acc[mi][ni][2 * h2 + 1];
                if (epi == 1) { v0 += bias[c]; v1 += bias[c + 1]; }
                else if (epi == 2) { v0 = gelu_exact(v0); v1 = gelu_exact(v1); }
                v0 *= scale; v1 *= scale;
                *(float2*)(C + row * ldc + c) = make_float2(v0, v1);
                if (Ch) {
                    uint32_t hw, lw;
                    split2(v0, v1, hw, lw);
                    *(uint32_t*)(Ch + row * ldc + c) = hw;
                    *(uint32_t*)(Cl + row * ldc + c) = lw;
                }
            }
        }
    }
}

// ---------------- batched fp16x3 HMMA for the score GEMMs ----------------
// z = 0..7: head h = z&3, half = z>>2.
// A = q splits, column offset (z&3)*256 + (z>>2)*128, lda = 1024, K = 128.
// B = folded sk splits slot z (128x128, ldb = 128).
// C = g_s + (z>>2)*SOFF + (z&3)*128, ldc = 512; bias = g_bs + z*128.
__global__ void __launch_bounds__(256, 2)
gemm_h3s(const __half* __restrict__ qh, const __half* __restrict__ ql,
         const __half* __restrict__ skh, const __half* __restrict__ skl,
         float* __restrict__ sOut, const float* __restrict__ bs) {
    extern __shared__ uint32_t smu[];
    uint32_t smaddr = (uint32_t)__cvta_generic_to_shared(smu);

    int z = blockIdx.z;
    int aoff = (z & 3) * 256 + (z >> 2) * 128;
    const __half* Ah = qh + aoff;
    const __half* Al = ql + aoff;
    const __half* Bh = skh + z * 16384;
    const __half* Bl = skl + z * 16384;
    float* C = sOut + (size_t)(z >> 2) * SOFF + (z & 3) * 128;
    const float* bias = bs + z * 128;

    int tid = threadIdx.x;
    int lane = tid & 31;
    int wid = tid >> 5;
    int wm = (wid >> 2) * 64;
    int wn = (wid & 3) * 32;
    int g = lane >> 2, tg = lane & 3;
    int m0 = blockIdx.y * 128;

    float acc[4][4][4];
    #pragma unroll
    for (int mi = 0; mi < 4; mi++)
        #pragma unroll
        for (int ni = 0; ni < 4; ni++)
            #pragma unroll
            for (int t = 0; t < 4; t++) acc[mi][ni][t] = 0.0f;

    int qk = tid & 3;
    auto issue = [&](int s, int k0) {
        uint32_t base = smaddr + (uint32_t)(s * STAGE_U32) * 4;
        #pragma unroll
        for (int i = 0; i < 8; i++) {
            int mat = i >> 1;
            int r = (tid + 256 * (i & 1)) >> 2;
            const __half* gp;
            if (mat == 0)      gp = Ah + (size_t)(m0 + r) * 1024 + k0 + qk * 8;
            else if (mat == 1) gp = Al + (size_t)(m0 + r) * 1024 + k0 + qk * 8;
            else if (mat == 2) gp = Bh + (size_t)r * 128 + k0 + qk * 8;
            else               gp = Bl + (size_t)r * 128 + k0 + qk * 8;
            cp16(base + (uint32_t)(mat * MAT_U32 + r * HSTR + qk * 4) * 4, gp);
        }
    };

    const int nkt = 4;   // K = 128
    issue(0, 0);
    CP_COMMIT();
    issue(1, 32);
    CP_COMMIT();
    CP_WAIT1();
    __syncthreads();

    for (int kt = 0; kt < nkt; kt++) {
        int cur = kt & 1;
        const uint32_t* st = smu + cur * STAGE_U32;
        #pragma unroll
        for (int ks = 0; ks < 2; ks++) {
            int kc = ks * 8;
            uint32_t ah[4][4], al[4][4], bh[4][2], bl[4][2];
            #pragma unroll
            for (int mi = 0; mi < 4; mi++) {
                int r = wm + mi * 16 + g;
                ah[mi][0] = st[r * HSTR + kc + tg];
                ah[mi][1] = st[(r + 8) * HSTR + kc + tg];
                ah[mi][2] = st[r * HSTR + kc + tg + 4];
                ah[mi][3] = st[(r + 8) * HSTR + kc + tg + 4];
                al[mi][0] = st[MAT_U32 + r * HSTR + kc + tg];
                al[mi][1] = st[MAT_U32 + (r + 8) * HSTR + kc + tg];
                al[mi][2] = st[MAT_U32 + r * HSTR + kc + tg + 4];
                al[mi][3] = st[MAT_U32 + (r + 8) * HSTR + kc + tg + 4];
            }
            #pragma unroll
            for (int ni = 0; ni < 4; ni++) {
                int rn = wn + ni * 8 + g;
                bh[ni][0] = st[2 * MAT_U32 + rn * HSTR + kc + tg];
                bh[ni][1] = st[2 * MAT_U32 + rn * HSTR + kc + tg + 4];
                bl[ni][0] = st[3 * MAT_U32 + rn * HSTR + kc + tg];
                bl[ni][1] = st[3 * MAT_U32 + rn * HSTR + kc + tg + 4];
            }
            #pragma unroll
            for (int mi = 0; mi < 4; mi++)
                #pragma unroll
                for (int ni = 0; ni < 4; ni++) {
                    hmma(acc[mi][ni], ah[mi], bh[ni]);
                    hmma(acc[mi][ni], al[mi], bh[ni]);
                    hmma(acc[mi][ni], ah[mi], bl[ni]);
                }
        }
        if (kt + 1 < nkt) {
            __syncthreads();
            if (kt + 2 < nkt) { issue((kt + 2) & 1, (kt + 2) * 32); CP_COMMIT(); CP_WAIT1(); }
            else { CP_WAIT0(); }
            __syncthreads();
        }
    }

    #pragma unroll
    for (int mi = 0; mi < 4; mi++) {
        #pragma unroll
        for (int h2 = 0; h2 < 2; h2++) {
            size_t row = (size_t)(m0 + wm + mi * 16 + g + h2 * 8);
            #pragma unroll
            for (int ni = 0; ni < 4; ni++) {
                int c = wn + ni * 8 + 2 * tg;
                float v0 = acc[mi][ni][2 * h2] + bias[c];
                float v1 = acc[mi][ni][2 * h2 + 1] + bias[c + 1];
                *(float2*)(C + row * 512 + c) = make_float2(v0, v1);
            }
        }
    }
}

// ---------------- tiny utility kernels ----------------
__global__ void zero_stats_kernel() {
    int i = threadIdx.x;
    g_sum[i] = 0.0f;
    g_sqs[i] = 0.0f;
}

__global__ void bn_reduce_kernel() {
    int tid = threadIdx.x;             // 256
    int r0 = blockIdx.x * 64;          // 128 blocks
    float s0 = 0.f, s1 = 0.f, s2 = 0.f, s3 = 0.f;
    float q0 = 0.f, q1 = 0.f, q2 = 0.f, q3 = 0.f;
    for (int r = 0; r < 64; r++) {
        const float* row = g_q + (size_t)(r0 + r) * 1024;
        float v0 = row[tid];
        float v1 = row[tid + 256];
        float v2 = row[tid + 512];
        float v3 = row[tid + 768];
        s0 += v0; q0 += v0 * v0;
        s1 += v1; q1 += v1 * v1;
        s2 += v2; q2 += v2 * v2;
        s3 += v3; q3 += v3 * v3;
    }
    atomicAdd(&g_sum[tid],       s0);
    atomicAdd(&g_sum[tid + 256], s1);
    atomicAdd(&g_sum[tid + 512], s2);
    atomicAdd(&g_sum[tid + 768], s3);
    atomicAdd(&g_sqs[tid],       q0);
    atomicAdd(&g_sqs[tid + 256], q1);
    atomicAdd(&g_sqs[tid + 512], q2);
    atomicAdd(&g_sqs[tid + 768], q3);
}

__global__ void bn_finalize_kernel(const float* __restrict__ gamma,
                                   const float* __restrict__ beta) {
    int c = threadIdx.x;  // 1024
    float mean = g_sum[c] * (1.0f / NTOK);
    float var  = g_sqs[c] * (1.0f / NTOK) - mean * mean;
    float rstd = rsqrtf(var + BN_EPS);
    float a = gamma[c] * rstd;
    g_a[c] = a;
    g_b[c] = beta[c] - mean * a;
}

// fold BN affine into score weights; emit half hi/lo splits + exact fp32 bias.
// slot z = h for s1, z = 4 + h for s2.
__global__ void fold_sk_kernel(const float* __restrict__ sk1,
                               const float* __restrict__ sk2) {
    int h = blockIdx.x >> 7;      // 512 blocks
    int k = blockIdx.x & 127;
    int j = threadIdx.x;          // 128
    float w1 = sk1[k * 128 + j];
    float w2 = sk2[k * 128 + j];
    float a1 = g_a[h * 256 + j],       b1 = g_b[h * 256 + j];
    float a2 = g_a[h * 256 + 128 + j], b2 = g_b[h * 256 + 128 + j];

    float f1 = w1 * a1, f2 = w2 * a2;
    __half f1h = __float2half_rn(f1);
    __half f2h = __float2half_rn(f2);
    int z1 = h, z2 = 4 + h;
    g_skh[z1 * 16384 + k * 128 + j] = f1h;
    g_skl[z1 * 16384 + k * 128 + j] = __float2half_rn(f1 - __half2float(f1h));
    g_skh[z2 * 16384 + k * 128 + j] = f2h;
    g_skl[z2 * 16384 + k * 128 + j] = __float2half_rn(f2 - __half2float(f2h));

    float p1 = w1 * b1, p2 = w2 * b2;
    const unsigned FULL = 0xffffffffu;
    #pragma unroll
    for (int off = 16; off > 0; off >>= 1) {
        p1 += __shfl_down_sync(FULL, p1, off);
        p2 += __shfl_down_sync(FULL, p2, off);
    }
    __shared__ float sh[8];
    int w = j >> 5, l = j & 31;
    if (l == 0) { sh[w] = p1; sh[4 + w] = p2; }
    __syncthreads();
    if (j == 0) {
        g_bs[z1 * 128 + k] = sh[0] + sh[1] + sh[2] + sh[3];
        g_bs[z2 * 128 + k] = sh[4] + sh[5] + sh[6] + sh[7];
    }
}

// ---------------- top-k machinery: one warp per (n,h) ----------------
__global__ void __launch_bounds__(256) topk_kernel() {
    const unsigned FULL = 0xffffffffu;
    int gw = (blockIdx.x * 256 + threadIdx.x) >> 5;   // 0..32767
    int lane = threadIdx.x & 31;
    const float* p1 = g_s + (size_t)gw * 128;
    const float* p2 = g_s + SOFF + (size_t)gw * 128;

    float v1[4], v2[4];
    #pragma unroll
    for (int i = 0; i < 4; i++) {
        v1[i] = p1[lane + 32 * i];
        v2[i] = p2[lane + 32 * i];
    }

    float slot_v1 = 0.f, slot_v2 = 0.f;
    int   slot_i1 = 0,   slot_i2 = 0;
    #pragma unroll
    for (int t = 0; t < 16; t++) {
        {
            float bv = v1[0]; int bi = lane;
            #pragma unroll
            for (int i = 1; i < 4; i++)
                if (v1[i] > bv) { bv = v1[i]; bi = lane + 32 * i; }
            #pragma unroll
            for (int off = 16; off > 0; off >>= 1) {
                float ov = __shfl_down_sync(FULL, bv, off);
                int   oi = __shfl_down_sync(FULL, bi, off);
                if (ov > bv || (ov == bv && oi < bi)) { bv = ov; bi = oi; }
            }
            bv = __shfl_sync(FULL, bv, 0);
            bi = __shfl_sync(FULL, bi, 0);
            if (lane == t) { slot_v1 = bv; slot_i1 = bi; }
            int sl = bi >> 5, ol = bi & 31;
            if (lane == ol) {
                if      (sl == 0) v1[0] = -3.4e38f;
                else if (sl == 1) v1[1] = -3.4e38f;
                else if (sl == 2) v1[2] = -3.4e38f;
                else              v1[3] = -3.4e38f;
            }
        }
        {
            float bv = v2[0]; int bi = lane;
            #pragma unroll
            for (int i = 1; i < 4; i++)
                if (v2[i] > bv) { bv = v2[i]; bi = lane + 32 * i; }
            #pragma unroll
            for (int off = 16; off > 0; off >>= 1) {
                float ov = __shfl_down_sync(FULL, bv, off);
                int   oi = __shfl_down_sync(FULL, bi, off);
                if (ov > bv || (ov == bv && oi < bi)) { bv = ov; bi = oi; }
            }
            bv = __shfl_sync(FULL, bv, 0);
            bi = __shfl_sync(FULL, bi, 0);
            if (lane == t) { slot_v2 = bv; slot_i2 = bi; }
            int sl = bi >> 5, ol = bi & 31;
            if (lane == ol) {
                if      (sl == 0) v2[0] = -3.4e38f;
                else if (sl == 1) v2[1] = -3.4e38f;
                else if (sl == 2) v2[2] = -3.4e38f;
                else              v2[3] = -3.4e38f;
            }
        }
    }

    float cv[8];
    #pragma unroll
    for (int j = 0; j < 8; j++) {
        int c = lane + 32 * j;
        float a = __shfl_sync(FULL, slot_v1, c >> 4);
        float b = __shfl_sync(FULL, slot_v2, c & 15);
        cv[j] = a + b;
    }

    float sel_v = -3.4e38f; int sel_c = 0;
    #pragma unroll
    for (int t = 0; t < 8; t++) {
        float bv = cv[0]; int bc = lane;
        #pragma unroll
        for (int j = 1; j < 8; j++)
            if (cv[j] > bv) { bv = cv[j]; bc = lane + 32 * j; }
        #pragma unroll
        for (int off = 16; off > 0; off >>= 1) {
            float ov = __shfl_down_sync(FULL, bv, off);
            int   oc = __shfl_down_sync(FULL, bc, off);
            if (ov > bv || (ov == bv && oc < bc)) { bv = ov; bc = oc; }
        }
        bv = __shfl_sync(FULL, bv, 0);
        bc = __shfl_sync(FULL, bc, 0);
        if (lane == t) { sel_v = bv; sel_c = bc; }
        int sl = bc >> 5, ol = bc & 31;
        if (lane == ol) {
            switch (sl) {
                case 0: cv[0] = -3.4e38f; break;
                case 1: cv[1] = -3.4e38f; break;
                case 2: cv[2] = -3.4e38f; break;
                case 3: cv[3] = -3.4e38f; break;
                case 4: cv[4] = -3.4e38f; break;
                case 5: cv[5] = -3.4e38f; break;
                case 6: cv[6] = -3.4e38f; break;
                default: cv[7] = -3.4e38f; break;
            }
        }
    }

    float mv = (lane < 8) ? sel_v : -3.4e38f;
    #pragma unroll
    for (int off = 4; off > 0; off >>= 1)
        mv = fmaxf(mv, __shfl_xor_sync(FULL, mv, off));
    float ev = (lane < 8) ? expf(sel_v - mv) : 0.0f;
    float sum = ev;
    #pragma unroll
    for (int off = 4; off > 0; off >>= 1)
        sum += __shfl_xor_sync(FULL, sum, off);
    float p = ev / sum;

    int i1 = __shfl_sync(FULL, slot_i1, sel_c >> 4);
    int i2 = __shfl_sync(FULL, slot_i2, sel_c & 15);
    if (lane < 8) {
        g_probs[(size_t)gw * 8 + lane] = p;
        g_eidx [(size_t)gw * 8 + lane] = i1 * NSUB + i2;
    }
}

// ---------------- expert gather (writes acc as half hi/lo inline) ----------------
__global__ void __launch_bounds__(256) gather_kernel() {
    const unsigned FULL = 0xffffffffu;
    __shared__ float sx[DH];
    __shared__ float sacc[8][DH];
    int n = blockIdx.x;
    int tid = threadIdx.x;
    int w = tid >> 5, lane = tid & 31;

    sx[tid]       = g_xp[(size_t)n * DH + tid];
    sx[tid + 256] = g_xp[(size_t)n * DH + tid + 256];
    #pragma unroll
    for (int i = 0; i < 16; i++) sacc[w][lane + 32 * i] = 0.0f;
    __syncthreads();

    #pragma unroll
    for (int p = 0; p < 4; p++) {
        int idx = w * 4 + p;
        int e = g_eidx[(size_t)n * 32 + idx];
        float prob = g_probs[(size_t)n * 32 + idx];
        const float* hrow = g_H + (size_t)e * DH;
        float hv[16];
        float dot = 0.0f;
        #pragma unroll
        for (int i = 0; i < 16; i++) {
            hv[i] = hrow[lane + 32 * i];
            dot = fmaf(hv[i], sx[lane + 32 * i], dot);
        }
        #pragma unroll
        for (int off = 16; off > 0; off >>= 1)
            dot += __shfl_down_sync(FULL, dot, off);
        dot = __shfl_sync(FULL, dot, 0);
        float act = gelu_exact(dot) * prob;
        #pragma unroll
        for (int i = 0; i < 16; i++)
            sacc[w][lane + 32 * i] = fmaf(act, hv[i], sacc[w][lane + 32 * i]);
    }
    __syncthreads();

    for (int c = tid; c < DH; c += 256) {
        float s = 0.0f;
        #pragma unroll
        for (int ww = 0; ww < 8; ww++) s += sacc[ww][c];
        __half hh = __float2half_rn(s);
        g_acch[(size_t)n * DH + c] = hh;
        g_accl[(size_t)n * DH + c] = __float2half_rn(s - __half2float(hh));
    }
}

// ---------------- host launcher ----------------
extern "C" void kernel_launch(void* const* d_in, const int* in_sizes, int n_in,
                              void* d_out, int out_size) {
    (void)in_sizes; (void)n_in; (void)out_size;
    const float* x    = (const float*)d_in[0];
    const float* Wq   = (const float*)d_in[1];
    const float* bq   = (const float*)d_in[2];
    const float* gam  = (const float*)d_in[3];
    const float* bet  = (const float*)d_in[4];
    const float* sk1  = (const float*)d_in[5];
    const float* sk2  = (const float*)d_in[6];
    const float* lat  = (const float*)d_in[7];
    const float* W1   = (const float*)d_in[8];
    const float* W2   = (const float*)d_in[9];
    float* out = (float*)d_out;

    float *q, *sArr, *bs, *H, *xp;
    cudaGetSymbolAddress((void**)&q,    g_q);
    cudaGetSymbolAddress((void**)&sArr, g_s);
    cudaGetSymbolAddress((void**)&bs,   g_bs);
    cudaGetSymbolAddress((void**)&H,    g_H);
    cudaGetSymbolAddress((void**)&xp,   g_xp);

    __half *xh, *xl, *qh, *ql, *Wqh, *Wql, *lath, *latl, *W1Th, *W1Tl,
           *W2ph, *W2pl, *WvTh, *WvTl, *acch, *accl, *skh, *skl;
    cudaGetSymbolAddress((void**)&xh,   g_xh);
    cudaGetSymbolAddress((void**)&xl,   g_xl);
    cudaGetSymbolAddress((void**)&qh,   g_qh);
    cudaGetSymbolAddress((void**)&ql,   g_ql);
    cudaGetSymbolAddress((void**)&Wqh,  g_Wqh);
    cudaGetSymbolAddress((void**)&Wql,  g_Wql);
    cudaGetSymbolAddress((void**)&lath, g_lath);
    cudaGetSymbolAddress((void**)&latl, g_latl);
    cudaGetSymbolAddress((void**)&W1Th, g_W1Th);
    cudaGetSymbolAddress((void**)&W1Tl, g_W1Tl);
    cudaGetSymbolAddress((void**)&W2ph, g_W2ph);
    cudaGetSymbolAddress((void**)&W2pl, g_W2pl);
    cudaGetSymbolAddress((void**)&WvTh, g_WvTh);
    cudaGetSymbolAddress((void**)&WvTl, g_WvTl);
    cudaGetSymbolAddress((void**)&acch, g_acch);
    cudaGetSymbolAddress((void**)&accl, g_accl);
    cudaGetSymbolAddress((void**)&skh,  g_skh);
    cudaGetSymbolAddress((void**)&skl,  g_skl);

    const int h3_smem = 2 * STAGE_U32 * 4;   // 81920 bytes
    cudaFuncSetAttribute(gemm_h3b, cudaFuncAttributeMaxDynamicSharedMemorySize, h3_smem);
    cudaFuncSetAttribute(gemm_h3s, cudaFuncAttributeMaxDynamicSharedMemorySize, h3_smem);

    // 1. pre-split operands + zero BN stats
    zero_stats_kernel<<<1, 1024>>>();
    split_kernel<<<8192, 256>>>(x,   xh,   xl,   NTOK * DM / 4);
    split_kernel<<<1024, 256>>>(Wq,  Wqh,  Wql,  1024 * 1024 / 4);
    split_kernel<<<4096, 256>>>(lat, lath, latl, NEXP * DL / 4);
    transpose_split_kernel<<<dim3(16, 8),  dim3(32, 8)>>>(W1, W1Th, W1Tl, 256, 512, 512);
    transpose_split_kernel<<<dim3(32, 16), dim3(32, 8)>>>(W2 + 1024, WvTh, WvTl, 512, 1024, 2048);
    split_strided_kernel<<<512, 256>>>(W2, W2ph, W2pl, 512, 1024, 2048);

    // 2. q = x @ Wq^T + bq   (fp16x3 HMMA; epilogue also emits q hi/lo splits)
    gemm_h3b<<<dim3(8, 64), 256, h3_smem>>>(xh, xl, Wqh, Wql, q, bq,
                                            1024, 1024, 1024, 1024, 1, 1.0f,
                                            qh, ql);

    // 3-5. BN stats, fold affine into score weights (emits half splits + fp32 bias)
    bn_reduce_kernel<<<128, 256>>>();
    bn_finalize_kernel<<<1, 1024>>>(gam, bet);
    fold_sk_kernel<<<512, 128>>>(sk1, sk2);

    // 6. s1 and s2 in ONE batched fp16x3 HMMA launch (z = 8 slots)
    gemm_h3s<<<dim3(1, 64, 8), 256, h3_smem>>>(qh, ql, skh, skl, sArr, bs);

    // 7. top-16 x top-16 -> top-8, softmax, expert indices
    topk_kernel<<<4096, 256>>>();

    // 8. H = gelu(latents @ W1)   (fp16x3 HMMA)
    gemm_h3b<<<dim3(4, 128), 256, h3_smem>>>(lath, latl, W1Th, W1Tl, H, nullptr,
                                             256, 256, 256, 512, 2, 1.0f,
                                             nullptr, nullptr);

    // 9. x_proj = x @ W2[:, :1024]^T   (fp16x3 HMMA)
    gemm_h3b<<<dim3(4, 64), 256, h3_smem>>>(xh, xl, W2ph, W2pl, xp, nullptr,
                                            1024, 1024, 1024, 512, 0, 1.0f,
                                            nullptr, nullptr);

    // 10. gather experts (writes acc directly as half hi/lo)
    gather_kernel<<<NTOK, 256>>>();

    // 11. out = acc @ Wv / NUM_HEADS   (fp16x3 HMMA)
    gemm_h3b<<<dim3(8, 64), 256, h3_smem>>>(acch, accl, WvTh, WvTl, out, nullptr,
                                            512, 512, 512, 1024, 0, 0.25f,
                                            nullptr, nullptr);
}